// round 4
// baseline (speedup 1.0000x reference)
#include <cuda_runtime.h>
#include <cstdint>

#define LL   2
#define TT   512
#define BB   128
#define HH   256
#define CLSZ 8
#define NCL  16
#define NTHR 512

// ---------------- smem layout (float indices) ----------------
#define OFF_U    0          // [128 col][260 pad]           33280
#define OFF_HB   33280      // [2][256 h][8 b]               4096
#define OFF_PAR  37376      // [3 kq][128 col][8 b]          3072
#define OFF_PRE  40448      // [8 b][128 col]                1024
#define OFF_WX   41472      // [128 col][4 f]                 512
#define OFF_WB   41984      // [128 col]                      128
#define OFF_FW   42112      // [256 k][4 f]                  1024
#define OFF_FB   43136      // [4]                              4
#define OFF_YP   43140      // [8 src][4 f]                    32
#define OFF_MB   43172      // 4 mbarriers, byte off 172688 (8B aligned)
#define SMEM_FLOATS 43180
#define SMEM_BYTES (SMEM_FLOATS * 4)

#define MBB       (OFF_MB * 4)
#define MB_FULL0  (MBB + 0)
#define MB_FULL1  (MBB + 8)
#define MB_EMPTY0 (MBB + 16)
#define MB_EMPTY1 (MBB + 24)

__device__ float g_y1[TT * BB * 4];   // layer-1 output [T][B][4]

typedef unsigned long long ull;

__device__ __forceinline__ uint32_t smem_u32(const void* p) {
    uint32_t a;
    asm("{ .reg .u64 t; cvta.to.shared.u64 t, %1; cvt.u32.u64 %0, t; }"
        : "=r"(a) : "l"(p));
    return a;
}
__device__ __forceinline__ void cluster_sync() {
    asm volatile("barrier.cluster.arrive.aligned;" ::: "memory");
    asm volatile("barrier.cluster.wait.aligned;" ::: "memory");
}
__device__ __forceinline__ ull pack2(float a, float b) {
    ull r; asm("mov.b64 %0, {%1, %2};" : "=l"(r) : "f"(a), "f"(b)); return r;
}
__device__ __forceinline__ float2 unpack2(ull v) {
    float2 r; asm("mov.b64 {%0, %1}, %2;" : "=f"(r.x), "=f"(r.y) : "l"(v)); return r;
}
__device__ __forceinline__ ull ffma2(ull a, ull b, ull c) {
    ull d; asm("fma.rn.f32x2 %0, %1, %2, %3;" : "=l"(d) : "l"(a), "l"(b), "l"(c)); return d;
}
__device__ __forceinline__ ull add2(ull a, ull b) {
    ull d; asm("add.rn.f32x2 %0, %1, %2;" : "=l"(d) : "l"(a), "l"(b)); return d;
}
__device__ __forceinline__ float fsig(float x) {
    float e, r;
    asm("ex2.approx.f32 %0, %1;" : "=f"(e) : "f"(x * -1.4426950408889634f));
    asm("rcp.approx.f32 %0, %1;" : "=f"(r) : "f"(1.0f + e));
    return r;
}
__device__ __forceinline__ float ftanh(float x) {
    float e, r;
    asm("ex2.approx.f32 %0, %1;" : "=f"(e) : "f"(x * -2.8853900817779268f));
    asm("rcp.approx.f32 %0, %1;" : "=f"(r) : "f"(1.0f + e));
    return __fmaf_rn(2.0f, r, -1.0f);
}
__device__ __forceinline__ void mbar_init(uint32_t a, uint32_t c) {
    asm volatile("mbarrier.init.shared.b64 [%0], %1;" :: "r"(a), "r"(c) : "memory");
}
__device__ __forceinline__ void mbar_arrive_local(uint32_t a) {
    asm volatile("mbarrier.arrive.shared.b64 _, [%0];" :: "r"(a) : "memory");
}
__device__ __forceinline__ void mbar_arrive_remote(uint32_t a, uint32_t rank) {
    uint32_t ra;
    asm("mapa.shared::cluster.u32 %0, %1, %2;" : "=r"(ra) : "r"(a), "r"(rank));
    asm volatile("mbarrier.arrive.release.cluster.shared::cluster.b64 _, [%0];"
                 :: "r"(ra) : "memory");
}
__device__ __forceinline__ void mbar_wait(uint32_t a, uint32_t ph) {
    asm volatile(
        "{\n\t.reg .pred P;\n"
        "W0_%=:\n\t"
        "mbarrier.try_wait.parity.acquire.cluster.shared::cta.b64 P, [%0], %1, 0x989680;\n\t"
        "@P bra W1_%=;\n\t"
        "bra W0_%=;\n"
        "W1_%=:\n\t}"
        :: "r"(a), "r"(ph) : "memory");
}

#define QNEG_MASK 0x284E

__global__ void __launch_bounds__(NTHR, 1) __cluster_dims__(CLSZ, 1, 1)
qlstm_kernel(const float* __restrict__ x,
             const float* __restrict__ Wxr, const float* __restrict__ Wxi,
             const float* __restrict__ Wxj, const float* __restrict__ Wxk,
             const float* __restrict__ Wxb,
             const float* __restrict__ Ur,  const float* __restrict__ Ui,
             const float* __restrict__ Uj,  const float* __restrict__ Uk,
             const float* __restrict__ fcw, const float* __restrict__ fcb,
             float* __restrict__ out)
{
    extern __shared__ float sm[];
    float* sU   = sm + OFF_U;
    float* sHB  = sm + OFF_HB;
    float* sPar = sm + OFF_PAR;
    float* sPre = sm + OFF_PRE;
    float* sWx  = sm + OFF_WX;
    float* sWb  = sm + OFF_WB;
    float* sFW  = sm + OFF_FW;
    float* sFB  = sm + OFF_FB;
    float* sYP  = sm + OFF_YP;

    const int tid  = threadIdx.x;
    const int lane = tid & 31;
    const int wid  = tid >> 5;
    const int col  = tid & 127;
    const int kq   = tid >> 7;
    const int r    = blockIdx.x & 7;
    const int cid  = blockIdx.x >> 3;
    const int k    = lane;
    const int aw   = wid;              // producer warps 0..3 (tid<128)
    const int b0   = aw * 2;
    const int b1   = b0 + 1;
    const uint32_t sbase = smem_u32(sm);

    // ---- one-time init: barriers, zero h, prime ----
    if (tid == 0) {
        mbar_init(sbase + MB_FULL0, 32);
        mbar_init(sbase + MB_FULL1, 32);
        mbar_init(sbase + MB_EMPTY0, 8);
        mbar_init(sbase + MB_EMPTY1, 8);
    }
    for (int i = tid; i < 2 * 256 * 8; i += NTHR) sHB[i] = 0.0f;
    __syncthreads();
    if (tid < 32) mbar_arrive_local(sbase + MB_FULL0);   // prime full[0]
    if (tid < 8)  mbar_arrive_local(sbase + MB_EMPTY1);  // prime empty[1]
    cluster_sync();

    uint32_t pF0 = 0, pF1 = 0, pE0 = 0, pE1 = 0;
    float2 creg;

    for (int l = 0; l < LL; l++) {
        __syncthreads();

        // ---- gather U slice transposed+padded: sU[col*260 + h] ----
        for (int idx = tid; idx < 4 * 256 * 32; idx += NTHR) {
            int g   = idx >> 13;
            int rem = idx & 8191;
            int h   = rem >> 5;
            int kl  = rem & 31;
            int kg  = r * 32 + kl;
            int hb  = h >> 6, n = h & 63;
            int cb  = kg >> 6, m = kg & 63;
            int sel = hb ^ cb;
            float sgn = ((QNEG_MASK >> (cb * 4 + hb)) & 1) ? -1.0f : 1.0f;
            const float* cp = (sel == 0) ? Ur : (sel == 1) ? Ui : (sel == 2) ? Uj : Uk;
            sU[(g * 32 + kl) * 260 + h] =
                sgn * __ldg(&cp[((l * 4 + g) * 64 + n) * 64 + m]);
        }
        for (int idx = tid; idx < 512; idx += NTHR) {
            int g  = idx >> 7;
            int f  = (idx >> 5) & 3;
            int kl = idx & 31;
            int kg = r * 32 + kl;
            int cb = kg >> 6, m = kg & 63;
            int sel = f ^ cb;
            float sgn = ((QNEG_MASK >> (cb * 4 + f)) & 1) ? -1.0f : 1.0f;
            const float* cp = (sel == 0) ? Wxr : (sel == 1) ? Wxi : (sel == 2) ? Wxj : Wxk;
            sWx[(g * 32 + kl) * 4 + f] = sgn * __ldg(&cp[(l * 4 + g) * 64 + m]);
        }
        for (int idx = tid; idx < 128; idx += NTHR) {
            int g = idx >> 5, kl = idx & 31;
            sWb[idx] = Wxb[(l * 4 + g) * 256 + r * 32 + kl];
        }
        for (int idx = tid; idx < 1024; idx += NTHR)
            sFW[idx] = fcw[l * 1024 + idx];       // [256 k][4 f]
        if (tid < 4) sFB[tid] = fcb[l * 4 + tid];
        creg = make_float2(0.0f, 0.0f);
        __syncthreads();

        const float4* xp = (const float4*)((l == 0) ? x : g_y1);

        auto step = [&](int t, int buf, uint32_t phF, uint32_t phE) {
            const int nbuf = buf ^ 1;
            const uint32_t mb_full_n  = sbase + (nbuf ? MB_FULL1 : MB_FULL0);
            const uint32_t mb_empty_n = sbase + (nbuf ? MB_EMPTY1 : MB_EMPTY0);
            const uint32_t mb_empty_c = sbase + (buf ? MB_EMPTY1 : MB_EMPTY0);

            // wait for h_t (all threads)
            mbar_wait(sbase + (buf ? MB_FULL1 : MB_FULL0), phF);

            // ---- y-warp: y_{t-1} from full local h_t (layer 0 only) ----
            if (l == 0 && wid == 12 && t > 0) {
                const float* hb = sHB + buf * 2048;
                float s0 = 0.f, s1 = 0.f, s2 = 0.f, s3 = 0.f;
#pragma unroll
                for (int i = 0; i < 8; i++) {
                    int kk = lane + i * 32;
                    float hv = hb[kk * 8 + r];
                    float4 fw = *(const float4*)&sFW[kk * 4];
                    s0 += hv * fw.x; s1 += hv * fw.y;
                    s2 += hv * fw.z; s3 += hv * fw.w;
                }
#pragma unroll
                for (int m = 16; m >= 1; m >>= 1) {
                    s0 += __shfl_xor_sync(0xffffffffu, s0, m);
                    s1 += __shfl_xor_sync(0xffffffffu, s1, m);
                    s2 += __shfl_xor_sync(0xffffffffu, s2, m);
                    s3 += __shfl_xor_sync(0xffffffffu, s3, m);
                }
                if (lane == 0) {
                    s0 += sFB[0]; s1 += sFB[1]; s2 += sFB[2]; s3 += sFB[3];
                    float nn = s0 * s0 + s1 * s1 + s2 * s2 + s3 * s3;
                    float dn = fmaxf(sqrtf(nn), 1e-12f);
                    float iv = 1.0f / dn;
                    ((float4*)g_y1)[(t - 1) * BB + cid * 8 + r] =
                        make_float4(s0 * iv, s1 * iv, s2 * iv, s3 * iv);
                }
            }

            const float* hbc = sHB + buf * 2048 + kq * 512;
            const float* up  = sU + col * 260 + kq * 64;

            // ---- acc init ----
            ull A0, A1, A2, A3;
            if (kq == 0) {
                float4 wxc = *(const float4*)&sWx[col * 4];
                float  wbc = sWb[col];
                float acc[8];
#pragma unroll
                for (int j = 0; j < 8; j++) {
                    int xi = (l == 0) ? ((cid * 8 + j) * TT + t)
                                      : (t * BB + cid * 8 + j);
                    float4 xv = __ldg(&xp[xi]);
                    acc[j] = wbc + xv.x * wxc.x + xv.y * wxc.y
                                 + xv.z * wxc.z + xv.w * wxc.w;
                }
                A0 = pack2(acc[0], acc[1]); A1 = pack2(acc[2], acc[3]);
                A2 = pack2(acc[4], acc[5]); A3 = pack2(acc[6], acc[7]);
            } else {
                A0 = A1 = A2 = A3 = 0ull;
            }

            // ---- GEMM quarter: 64 h × 8 batches ----
#pragma unroll
            for (int hh = 0; hh < 64; hh += 4) {
                float4 u4 = *(const float4*)(up + hh);
                const float* hp = hbc + hh * 8;
                {
                    ull uu = pack2(u4.x, u4.x);
                    ulonglong2 a = *(const ulonglong2*)(hp);
                    ulonglong2 b = *(const ulonglong2*)(hp + 4);
                    A0 = ffma2(a.x, uu, A0); A1 = ffma2(a.y, uu, A1);
                    A2 = ffma2(b.x, uu, A2); A3 = ffma2(b.y, uu, A3);
                }
                {
                    ull uu = pack2(u4.y, u4.y);
                    ulonglong2 a = *(const ulonglong2*)(hp + 8);
                    ulonglong2 b = *(const ulonglong2*)(hp + 12);
                    A0 = ffma2(a.x, uu, A0); A1 = ffma2(a.y, uu, A1);
                    A2 = ffma2(b.x, uu, A2); A3 = ffma2(b.y, uu, A3);
                }
                {
                    ull uu = pack2(u4.z, u4.z);
                    ulonglong2 a = *(const ulonglong2*)(hp + 16);
                    ulonglong2 b = *(const ulonglong2*)(hp + 20);
                    A0 = ffma2(a.x, uu, A0); A1 = ffma2(a.y, uu, A1);
                    A2 = ffma2(b.x, uu, A2); A3 = ffma2(b.y, uu, A3);
                }
                {
                    ull uu = pack2(u4.w, u4.w);
                    ulonglong2 a = *(const ulonglong2*)(hp + 24);
                    ulonglong2 b = *(const ulonglong2*)(hp + 28);
                    A0 = ffma2(a.x, uu, A0); A1 = ffma2(a.y, uu, A1);
                    A2 = ffma2(b.x, uu, A2); A3 = ffma2(b.y, uu, A3);
                }
            }

            if (kq != 0) {
                float* pp = sPar + (kq - 1) * 1024 + col * 8;
                ((ulonglong2*)pp)[0] = make_ulonglong2(A0, A1);
                ((ulonglong2*)(pp + 4))[0] = make_ulonglong2(A2, A3);
            }
            __syncthreads();   // all local reads of sHB[buf] + partials done

            // ---- release this CTA's read of sHB[buf] to all writers ----
            if (tid == 128) {
#pragma unroll
                for (int j = 0; j < CLSZ; j++) mbar_arrive_remote(mb_empty_c, j);
            }

            // ---- combine + scatter ----
            if (tid < 128) {
#pragma unroll
                for (int q = 0; q < 3; q++) {
                    const float* pp = sPar + q * 1024 + col * 8;
                    ulonglong2 a = *(const ulonglong2*)(pp);
                    ulonglong2 b = *(const ulonglong2*)(pp + 4);
                    A0 = add2(A0, a.x); A1 = add2(A1, a.y);
                    A2 = add2(A2, b.x); A3 = add2(A3, b.y);
                }
                float2 v;
                v = unpack2(A0); sPre[0 * 128 + col] = v.x; sPre[1 * 128 + col] = v.y;
                v = unpack2(A1); sPre[2 * 128 + col] = v.x; sPre[3 * 128 + col] = v.y;
                v = unpack2(A2); sPre[4 * 128 + col] = v.x; sPre[5 * 128 + col] = v.y;
                v = unpack2(A3); sPre[6 * 128 + col] = v.x; sPre[7 * 128 + col] = v.y;
            }
            __syncthreads();

            if (tid < 128) {
                float hn0, hn1;
                {
                    const float* pb = sPre + b0 * 128 + k;
                    float ft = fsig(pb[0]);
                    float it = fsig(pb[32]);
                    float ot = fsig(pb[64]);
                    float ct = ftanh(pb[96]);
                    float c  = it * ct + ft * creg.x;
                    creg.x = c;
                    hn0 = ot * ftanh(c);
                }
                {
                    const float* pb = sPre + b1 * 128 + k;
                    float ft = fsig(pb[0]);
                    float it = fsig(pb[32]);
                    float ot = fsig(pb[64]);
                    float ct = ftanh(pb[96]);
                    float c  = it * ct + ft * creg.y;
                    creg.y = c;
                    hn1 = ot * ftanh(c);
                }

                // wait until everyone released sHB[nbuf], then broadcast
                mbar_wait(mb_empty_n, phE);
                {
                    // last step broadcasts zeros: re-zeros h for next layer
                    ull hh = (t == TT - 1) ? 0ull : pack2(hn0, hn1);
                    uint32_t haddr = sbase +
                        (OFF_HB + nbuf * 2048 + (r * 32 + k) * 8 + b0) * 4;
#pragma unroll
                    for (int j = 0; j < CLSZ; j++) {
                        uint32_t ra;
                        asm("mapa.shared::cluster.u32 %0, %1, %2;"
                            : "=r"(ra) : "r"(haddr), "r"(j));
                        asm volatile("st.shared::cluster.b64 [%0], %1;"
                                     :: "r"(ra), "l"(hh) : "memory");
                    }
                }
                __syncwarp();
                if (lane == 0) {
#pragma unroll
                    for (int j = 0; j < CLSZ; j++) mbar_arrive_remote(mb_full_n, j);
                }

                // ---- last step: exchange fco partials for y_{T-1} ----
                if (t == TT - 1) {
                    float4 fw = *(const float4*)&sFW[(r * 32 + k) * 4];
                    float v00 = hn0 * fw.x, v01 = hn0 * fw.y,
                          v02 = hn0 * fw.z, v03 = hn0 * fw.w;
                    float v10 = hn1 * fw.x, v11 = hn1 * fw.y,
                          v12 = hn1 * fw.z, v13 = hn1 * fw.w;
#pragma unroll
                    for (int m = 16; m >= 1; m >>= 1) {
                        v00 += __shfl_xor_sync(0xffffffffu, v00, m);
                        v01 += __shfl_xor_sync(0xffffffffu, v01, m);
                        v02 += __shfl_xor_sync(0xffffffffu, v02, m);
                        v03 += __shfl_xor_sync(0xffffffffu, v03, m);
                        v10 += __shfl_xor_sync(0xffffffffu, v10, m);
                        v11 += __shfl_xor_sync(0xffffffffu, v11, m);
                        v12 += __shfl_xor_sync(0xffffffffu, v12, m);
                        v13 += __shfl_xor_sync(0xffffffffu, v13, m);
                    }
                    if (lane == 0) {
                        uint32_t ya = sbase + (OFF_YP + r * 4) * 4;
                        ull q0 = pack2(v00, v01), q1 = pack2(v02, v03);
                        uint32_t ra;
                        asm("mapa.shared::cluster.u32 %0, %1, %2;"
                            : "=r"(ra) : "r"(ya), "r"(b0));
                        asm volatile("st.shared::cluster.b64 [%0], %1;"
                                     :: "r"(ra), "l"(q0) : "memory");
                        asm volatile("st.shared::cluster.b64 [%0], %1;"
                                     :: "r"(ra + 8), "l"(q1) : "memory");
                        q0 = pack2(v10, v11); q1 = pack2(v12, v13);
                        asm("mapa.shared::cluster.u32 %0, %1, %2;"
                            : "=r"(ra) : "r"(ya), "r"(b1));
                        asm volatile("st.shared::cluster.b64 [%0], %1;"
                                     :: "r"(ra), "l"(q0) : "memory");
                        asm volatile("st.shared::cluster.b64 [%0], %1;"
                                     :: "r"(ra + 8), "l"(q1) : "memory");
                    }
                }
            }

            if (t == TT - 1) {
                cluster_sync();
                if (tid < 32) {
                    float v = sYP[tid];
                    v += __shfl_xor_sync(0xffffffffu, v, 4);
                    v += __shfl_xor_sync(0xffffffffu, v, 8);
                    v += __shfl_xor_sync(0xffffffffu, v, 16);
                    v += sFB[tid & 3];
                    float nn = v * v;
                    nn += __shfl_xor_sync(0xffffffffu, nn, 1);
                    nn += __shfl_xor_sync(0xffffffffu, nn, 2);
                    float dn = fmaxf(sqrtf(nn), 1e-12f);
                    float yv = v / dn;
                    if (tid < 4) {
                        if (l == 0)
                            g_y1[((TT - 1) * BB + cid * 8 + r) * 4 + tid] = yv;
                        else
                            out[(cid * 8 + r) * 4 + tid] = yv;
                    }
                }
            }
        };

        for (int t2 = 0; t2 < TT; t2 += 2) {
            step(t2,     0, pF0, pE1); pF0 ^= 1; pE1 ^= 1;
            step(t2 + 1, 1, pF1, pE0); pF1 ^= 1; pE0 ^= 1;
        }
    } // l

    cluster_sync();
}

extern "C" void kernel_launch(void* const* d_in, const int* in_sizes, int n_in,
                              void* d_out, int out_size)
{
    (void)in_sizes; (void)n_in; (void)out_size;
    cudaFuncSetAttribute(qlstm_kernel,
                         cudaFuncAttributeMaxDynamicSharedMemorySize, SMEM_BYTES);
    qlstm_kernel<<<NCL * CLSZ, NTHR, SMEM_BYTES>>>(
        (const float*)d_in[0],
        (const float*)d_in[1], (const float*)d_in[2],
        (const float*)d_in[3], (const float*)d_in[4],
        (const float*)d_in[5],
        (const float*)d_in[6], (const float*)d_in[7],
        (const float*)d_in[8], (const float*)d_in[9],
        (const float*)d_in[10], (const float*)d_in[11],
        (float*)d_out);
}

// round 5
// speedup vs baseline: 1.5765x; 1.5765x over previous
#include <cuda_runtime.h>
#include <cstdint>

#define LL   2
#define TT   512
#define BB   128
#define HH   256
#define CLSZ 8
#define NCL  16
#define NTHR 512

// ---------------- smem layout (float indices) ----------------
#define OFF_U    0          // [128 col][260 pad h]         33280
#define OFF_HB   33280      // [2][256 h][8 b]               4096
#define OFF_PAR  37376      // [4 kq][8 b][128 col]          4096
#define OFF_WX   41472      // [128 col][4 f]                 512
#define OFF_WB   41984      // [128 col]                      128
#define OFF_FW   42112      // [256 k][4 f]                  1024
#define OFF_FB   43136      // [4]                              4
#define OFF_YP   43140      // [8 src][4 f]                    32
#define SMEM_FLOATS 43172
#define SMEM_BYTES (SMEM_FLOATS * 4)

// layer-1 output scratch, TRANSPOSED: [B][T][4] (L1-friendly reads in layer 1)
__device__ float g_y1[BB * TT * 4];

typedef unsigned long long ull;

__device__ __forceinline__ uint32_t smem_u32(const void* p) {
    uint32_t a;
    asm("{ .reg .u64 t; cvta.to.shared.u64 t, %1; cvt.u32.u64 %0, t; }"
        : "=r"(a) : "l"(p));
    return a;
}
__device__ __forceinline__ void cluster_sync() {
    asm volatile("barrier.cluster.arrive.aligned;" ::: "memory");
    asm volatile("barrier.cluster.wait.aligned;" ::: "memory");
}
__device__ __forceinline__ ull pack2(float a, float b) {
    ull r; asm("mov.b64 %0, {%1, %2};" : "=l"(r) : "f"(a), "f"(b)); return r;
}
__device__ __forceinline__ float2 unpack2(ull v) {
    float2 r; asm("mov.b64 {%0, %1}, %2;" : "=f"(r.x), "=f"(r.y) : "l"(v)); return r;
}
__device__ __forceinline__ ull ffma2(ull a, ull b, ull c) {
    ull d; asm("fma.rn.f32x2 %0, %1, %2, %3;" : "=l"(d) : "l"(a), "l"(b), "l"(c)); return d;
}
__device__ __forceinline__ float fsig(float x) {
    float e, r;
    asm("ex2.approx.f32 %0, %1;" : "=f"(e) : "f"(x * -1.4426950408889634f));
    asm("rcp.approx.f32 %0, %1;" : "=f"(r) : "f"(1.0f + e));
    return r;
}
__device__ __forceinline__ float ftanh(float x) {
    float e, r;
    asm("ex2.approx.f32 %0, %1;" : "=f"(e) : "f"(x * -2.8853900817779268f));
    asm("rcp.approx.f32 %0, %1;" : "=f"(r) : "f"(1.0f + e));
    return __fmaf_rn(2.0f, r, -1.0f);
}

#define QNEG_MASK 0x284E

__global__ void __launch_bounds__(NTHR, 1) __cluster_dims__(CLSZ, 1, 1)
qlstm_kernel(const float* __restrict__ x,
             const float* __restrict__ Wxr, const float* __restrict__ Wxi,
             const float* __restrict__ Wxj, const float* __restrict__ Wxk,
             const float* __restrict__ Wxb,
             const float* __restrict__ Ur,  const float* __restrict__ Ui,
             const float* __restrict__ Uj,  const float* __restrict__ Uk,
             const float* __restrict__ fcw, const float* __restrict__ fcb,
             float* __restrict__ out)
{
    extern __shared__ float sm[];
    float* sU   = sm + OFF_U;
    float* sHB  = sm + OFF_HB;
    float* sPar = sm + OFF_PAR;
    float* sWx  = sm + OFF_WX;
    float* sWb  = sm + OFF_WB;
    float* sFW  = sm + OFF_FW;
    float* sFB  = sm + OFF_FB;
    float* sYP  = sm + OFF_YP;

    const int tid  = threadIdx.x;
    const int lane = tid & 31;
    const int wid  = tid >> 5;
    const int col  = tid & 127;        // GEMM column
    const int kq   = tid >> 7;         // split-K quarter
    const int r    = blockIdx.x & 7;
    const int cid  = blockIdx.x >> 3;
    const int k    = lane;             // activation k (tid<128)
    const int b0   = wid * 2;          // activation batch pair (warps 0..3)
    const int b1   = b0 + 1;
    const uint32_t sbase = smem_u32(sm);

    float2 creg;

    for (int l = 0; l < LL; l++) {
        __syncthreads();  // previous-phase readers done

        // ---- gather U slice transposed+padded: sU[col*260 + h] ----
        for (int idx = tid; idx < 4 * 256 * 32; idx += NTHR) {
            int g   = idx >> 13;
            int rem = idx & 8191;
            int h   = rem >> 5;
            int kl  = rem & 31;
            int kg  = r * 32 + kl;
            int hb  = h >> 6, n = h & 63;
            int cb  = kg >> 6, m = kg & 63;
            int sel = hb ^ cb;
            float sgn = ((QNEG_MASK >> (cb * 4 + hb)) & 1) ? -1.0f : 1.0f;
            const float* cp = (sel == 0) ? Ur : (sel == 1) ? Ui : (sel == 2) ? Uj : Uk;
            sU[(g * 32 + kl) * 260 + h] =
                sgn * __ldg(&cp[((l * 4 + g) * 64 + n) * 64 + m]);
        }
        for (int idx = tid; idx < 512; idx += NTHR) {
            int g  = idx >> 7;
            int f  = (idx >> 5) & 3;
            int kl = idx & 31;
            int kg = r * 32 + kl;
            int cb = kg >> 6, m = kg & 63;
            int sel = f ^ cb;
            float sgn = ((QNEG_MASK >> (cb * 4 + f)) & 1) ? -1.0f : 1.0f;
            const float* cp = (sel == 0) ? Wxr : (sel == 1) ? Wxi : (sel == 2) ? Wxj : Wxk;
            sWx[(g * 32 + kl) * 4 + f] = sgn * __ldg(&cp[(l * 4 + g) * 64 + m]);
        }
        for (int idx = tid; idx < 128; idx += NTHR) {
            int g = idx >> 5, kl = idx & 31;
            sWb[idx] = Wxb[(l * 4 + g) * 256 + r * 32 + kl];
        }
        for (int idx = tid; idx < 1024; idx += NTHR)
            sFW[idx] = fcw[l * 1024 + idx];            // [256 k][4 f]
        if (tid < 4) sFB[tid] = fcb[l * 4 + tid];
        // zero both h buffers (h_0 = 0)
        for (int i = tid; i < 2 * 256 * 8; i += NTHR) sHB[i] = 0.0f;
        creg = make_float2(0.0f, 0.0f);

        cluster_sync();   // tables + zeros visible cluster-wide

        const float4* xp = (const float4*)((l == 0) ? x : g_y1);  // both [B][T][4]

        for (int t = 0; t < TT; t++) {
            const int cur = t & 1;
            const int nxt = cur ^ 1;
            const float* hbc = sHB + cur * 2048 + kq * 512;
            const float* up  = sU + col * 260 + kq * 64;

            // ---- y-warp: y_{t-1} = norm(fco(h_state_t)) for this CTA's batch
            //      (layer 0 only; overlaps other warps' GEMM) ----
            if (l == 0 && wid == 15 && t > 0) {
                const float* hb = sHB + cur * 2048;
                float s0 = 0.f, s1 = 0.f, s2 = 0.f, s3 = 0.f;
#pragma unroll
                for (int i = 0; i < 8; i++) {
                    int kk = lane + i * 32;
                    float hv = hb[kk * 8 + r];
                    float4 fw = *(const float4*)&sFW[kk * 4];
                    s0 += hv * fw.x; s1 += hv * fw.y;
                    s2 += hv * fw.z; s3 += hv * fw.w;
                }
#pragma unroll
                for (int m = 16; m >= 1; m >>= 1) {
                    s0 += __shfl_xor_sync(0xffffffffu, s0, m);
                    s1 += __shfl_xor_sync(0xffffffffu, s1, m);
                    s2 += __shfl_xor_sync(0xffffffffu, s2, m);
                    s3 += __shfl_xor_sync(0xffffffffu, s3, m);
                }
                if (lane == 0) {
                    s0 += sFB[0]; s1 += sFB[1]; s2 += sFB[2]; s3 += sFB[3];
                    float nn = s0 * s0 + s1 * s1 + s2 * s2 + s3 * s3;
                    float iv = 1.0f / fmaxf(sqrtf(nn), 1e-12f);
                    ((float4*)g_y1)[(cid * 8 + r) * TT + (t - 1)] =
                        make_float4(s0 * iv, s1 * iv, s2 * iv, s3 * iv);
                }
            }

            // ---- acc init: kq==0 adds bias + x_t @ Wx ----
            ull A0, A1, A2, A3;
            if (kq == 0) {
                float4 wxc = *(const float4*)&sWx[col * 4];
                float  wbc = sWb[col];
                float acc[8];
#pragma unroll
                for (int j = 0; j < 8; j++) {
                    float4 xv = __ldg(&xp[(cid * 8 + j) * TT + t]);
                    acc[j] = wbc + xv.x * wxc.x + xv.y * wxc.y
                                 + xv.z * wxc.z + xv.w * wxc.w;
                }
                A0 = pack2(acc[0], acc[1]); A1 = pack2(acc[2], acc[3]);
                A2 = pack2(acc[4], acc[5]); A3 = pack2(acc[6], acc[7]);
            } else {
                A0 = A1 = A2 = A3 = 0ull;
            }

            // ---- GEMM quarter: 64 h × 8 batches ----
#pragma unroll
            for (int hh = 0; hh < 64; hh += 4) {
                float4 u4 = *(const float4*)(up + hh);
                const float* hp = hbc + hh * 8;
                {
                    ull uu = pack2(u4.x, u4.x);
                    ulonglong2 a = *(const ulonglong2*)(hp);
                    ulonglong2 b = *(const ulonglong2*)(hp + 4);
                    A0 = ffma2(a.x, uu, A0); A1 = ffma2(a.y, uu, A1);
                    A2 = ffma2(b.x, uu, A2); A3 = ffma2(b.y, uu, A3);
                }
                {
                    ull uu = pack2(u4.y, u4.y);
                    ulonglong2 a = *(const ulonglong2*)(hp + 8);
                    ulonglong2 b = *(const ulonglong2*)(hp + 12);
                    A0 = ffma2(a.x, uu, A0); A1 = ffma2(a.y, uu, A1);
                    A2 = ffma2(b.x, uu, A2); A3 = ffma2(b.y, uu, A3);
                }
                {
                    ull uu = pack2(u4.z, u4.z);
                    ulonglong2 a = *(const ulonglong2*)(hp + 16);
                    ulonglong2 b = *(const ulonglong2*)(hp + 20);
                    A0 = ffma2(a.x, uu, A0); A1 = ffma2(a.y, uu, A1);
                    A2 = ffma2(b.x, uu, A2); A3 = ffma2(b.y, uu, A3);
                }
                {
                    ull uu = pack2(u4.w, u4.w);
                    ulonglong2 a = *(const ulonglong2*)(hp + 24);
                    ulonglong2 b = *(const ulonglong2*)(hp + 28);
                    A0 = ffma2(a.x, uu, A0); A1 = ffma2(a.y, uu, A1);
                    A2 = ffma2(b.x, uu, A2); A3 = ffma2(b.y, uu, A3);
                }
            }

            // ---- all quarters write partials: sPar[kq][b][col] (conflict-free) ----
            {
                float* pp = sPar + kq * 1024 + col;
                float2 v;
                v = unpack2(A0); pp[0 * 128] = v.x; pp[1 * 128] = v.y;
                v = unpack2(A1); pp[2 * 128] = v.x; pp[3 * 128] = v.y;
                v = unpack2(A2); pp[4 * 128] = v.x; pp[5 * 128] = v.y;
                v = unpack2(A3); pp[6 * 128] = v.x; pp[7 * 128] = v.y;
            }
            __syncthreads();

            // ---- combine + activations + cell update + broadcast (tid<128) ----
            if (tid < 128) {
                float hn0, hn1;
#pragma unroll
                for (int bi = 0; bi < 2; bi++) {
                    const int b = bi ? b1 : b0;
                    const float* pb = sPar + b * 128 + k;
                    float pf = 0.f, pi = 0.f, po = 0.f, pc = 0.f;
#pragma unroll
                    for (int q = 0; q < 4; q++) {
                        const float* pq = pb + q * 1024;
                        pf += pq[0];
                        pi += pq[32];
                        po += pq[64];
                        pc += pq[96];
                    }
                    float ft = fsig(pf);
                    float it = fsig(pi);
                    float ot = fsig(po);
                    float ct = ftanh(pc);
                    float cold = bi ? creg.y : creg.x;
                    float c  = it * ct + ft * cold;
                    if (bi) creg.y = c; else creg.x = c;
                    float hn = ot * ftanh(c);
                    if (bi) hn1 = hn; else hn0 = hn;
                }

                // broadcast h slice to all 8 CTAs (DSMEM)
                {
                    ull hh = pack2(hn0, hn1);
                    uint32_t haddr = sbase +
                        (OFF_HB + nxt * 2048 + (r * 32 + k) * 8 + b0) * 4;
#pragma unroll
                    for (int j = 0; j < CLSZ; j++) {
                        uint32_t ra;
                        asm("mapa.shared::cluster.u32 %0, %1, %2;"
                            : "=r"(ra) : "r"(haddr), "r"(j));
                        asm volatile("st.shared::cluster.b64 [%0], %1;"
                                     :: "r"(ra), "l"(hh) : "memory");
                    }
                }

                // ---- last step only: exchange fco partials for y_{T-1} ----
                if (t == TT - 1) {
                    float4 fw = *(const float4*)&sFW[(r * 32 + k) * 4];
                    float v00 = hn0 * fw.x, v01 = hn0 * fw.y,
                          v02 = hn0 * fw.z, v03 = hn0 * fw.w;
                    float v10 = hn1 * fw.x, v11 = hn1 * fw.y,
                          v12 = hn1 * fw.z, v13 = hn1 * fw.w;
#pragma unroll
                    for (int m = 16; m >= 1; m >>= 1) {
                        v00 += __shfl_xor_sync(0xffffffffu, v00, m);
                        v01 += __shfl_xor_sync(0xffffffffu, v01, m);
                        v02 += __shfl_xor_sync(0xffffffffu, v02, m);
                        v03 += __shfl_xor_sync(0xffffffffu, v03, m);
                        v10 += __shfl_xor_sync(0xffffffffu, v10, m);
                        v11 += __shfl_xor_sync(0xffffffffu, v11, m);
                        v12 += __shfl_xor_sync(0xffffffffu, v12, m);
                        v13 += __shfl_xor_sync(0xffffffffu, v13, m);
                    }
                    if (lane == 0) {
                        uint32_t ya = sbase + (OFF_YP + r * 4) * 4;
                        ull q0 = pack2(v00, v01), q1 = pack2(v02, v03);
                        uint32_t ra;
                        asm("mapa.shared::cluster.u32 %0, %1, %2;"
                            : "=r"(ra) : "r"(ya), "r"(b0));
                        asm volatile("st.shared::cluster.b64 [%0], %1;"
                                     :: "r"(ra), "l"(q0) : "memory");
                        asm volatile("st.shared::cluster.b64 [%0], %1;"
                                     :: "r"(ra + 8), "l"(q1) : "memory");
                        q0 = pack2(v10, v11); q1 = pack2(v12, v13);
                        asm("mapa.shared::cluster.u32 %0, %1, %2;"
                            : "=r"(ra) : "r"(ya), "r"(b1));
                        asm volatile("st.shared::cluster.b64 [%0], %1;"
                                     :: "r"(ra), "l"(q0) : "memory");
                        asm volatile("st.shared::cluster.b64 [%0], %1;"
                                     :: "r"(ra + 8), "l"(q1) : "memory");
                    }
                }
            }

            cluster_sync();

            if (t == TT - 1 && tid < 32) {
                float v = sYP[tid];
                v += __shfl_xor_sync(0xffffffffu, v, 4);
                v += __shfl_xor_sync(0xffffffffu, v, 8);
                v += __shfl_xor_sync(0xffffffffu, v, 16);
                v += sFB[tid & 3];
                float nn = v * v;
                nn += __shfl_xor_sync(0xffffffffu, nn, 1);
                nn += __shfl_xor_sync(0xffffffffu, nn, 2);
                float yv = v / fmaxf(sqrtf(nn), 1e-12f);
                if (tid < 4) {
                    if (l == 0)
                        g_y1[((cid * 8 + r) * TT + (TT - 1)) * 4 + tid] = yv;
                    else
                        out[(cid * 8 + r) * 4 + tid] = yv;
                }
            }
        } // t
    } // l
}

extern "C" void kernel_launch(void* const* d_in, const int* in_sizes, int n_in,
                              void* d_out, int out_size)
{
    (void)in_sizes; (void)n_in; (void)out_size;
    cudaFuncSetAttribute(qlstm_kernel,
                         cudaFuncAttributeMaxDynamicSharedMemorySize, SMEM_BYTES);
    qlstm_kernel<<<NCL * CLSZ, NTHR, SMEM_BYTES>>>(
        (const float*)d_in[0],
        (const float*)d_in[1], (const float*)d_in[2],
        (const float*)d_in[3], (const float*)d_in[4],
        (const float*)d_in[5],
        (const float*)d_in[6], (const float*)d_in[7],
        (const float*)d_in[8], (const float*)d_in[9],
        (const float*)d_in[10], (const float*)d_in[11],
        (float*)d_out);
}

// round 6
// speedup vs baseline: 1.8517x; 1.1746x over previous
#include <cuda_runtime.h>
#include <cstdint>

#define LL   2
#define TT   512
#define BB   128
#define HH   256
#define CLSZ 8
#define NCL  16
#define NTHR 512

// ---------------- smem layout (float indices) ----------------
#define OFF_U    0          // [128 col][260 pad h]         33280
#define OFF_HB   33280      // [256 h][8 b]                  2048
#define OFF_OUT  35328      // [2 parity][32 k][8 b]          512
#define OFF_PAR  35840      // [4 kq][8 b][128 col]          4096
#define OFF_WX   39936      // [128 col][4 f]                 512
#define OFF_WB   40448      // [128 col]                      128
#define OFF_FW   40576      // [256 k][4 f]                  1024
#define OFF_FB   41600      // [4]                              4
#define SMEM_FLOATS 41604
#define SMEM_BYTES (SMEM_FLOATS * 4)

// layer-1 output scratch, TRANSPOSED: [B][T][4]
__device__ float g_y1[BB * TT * 4];

typedef unsigned long long ull;

__device__ __forceinline__ uint32_t smem_u32(const void* p) {
    uint32_t a;
    asm("{ .reg .u64 t; cvta.to.shared.u64 t, %1; cvt.u32.u64 %0, t; }"
        : "=r"(a) : "l"(p));
    return a;
}
__device__ __forceinline__ void cluster_sync() {
    asm volatile("barrier.cluster.arrive.aligned;" ::: "memory");
    asm volatile("barrier.cluster.wait.aligned;" ::: "memory");
}
__device__ __forceinline__ ull pack2(float a, float b) {
    ull r; asm("mov.b64 %0, {%1, %2};" : "=l"(r) : "f"(a), "f"(b)); return r;
}
__device__ __forceinline__ float2 unpack2(ull v) {
    float2 r; asm("mov.b64 {%0, %1}, %2;" : "=f"(r.x), "=f"(r.y) : "l"(v)); return r;
}
__device__ __forceinline__ ull ffma2(ull a, ull b, ull c) {
    ull d; asm("fma.rn.f32x2 %0, %1, %2, %3;" : "=l"(d) : "l"(a), "l"(b), "l"(c)); return d;
}
__device__ __forceinline__ float fsig(float x) {
    float e, r;
    asm("ex2.approx.f32 %0, %1;" : "=f"(e) : "f"(x * -1.4426950408889634f));
    asm("rcp.approx.f32 %0, %1;" : "=f"(r) : "f"(1.0f + e));
    return r;
}
__device__ __forceinline__ float ftanh(float x) {
    float e, r;
    asm("ex2.approx.f32 %0, %1;" : "=f"(e) : "f"(x * -2.8853900817779268f));
    asm("rcp.approx.f32 %0, %1;" : "=f"(r) : "f"(1.0f + e));
    return __fmaf_rn(2.0f, r, -1.0f);
}

#define QNEG_MASK 0x284E

__global__ void __launch_bounds__(NTHR, 1) __cluster_dims__(CLSZ, 1, 1)
qlstm_kernel(const float* __restrict__ x,
             const float* __restrict__ Wxr, const float* __restrict__ Wxi,
             const float* __restrict__ Wxj, const float* __restrict__ Wxk,
             const float* __restrict__ Wxb,
             const float* __restrict__ Ur,  const float* __restrict__ Ui,
             const float* __restrict__ Uj,  const float* __restrict__ Uk,
             const float* __restrict__ fcw, const float* __restrict__ fcb,
             float* __restrict__ out)
{
    extern __shared__ float sm[];
    float* sU   = sm + OFF_U;
    float* sHB  = sm + OFF_HB;
    float* sOut = sm + OFF_OUT;
    float* sPar = sm + OFF_PAR;
    float* sWx  = sm + OFF_WX;
    float* sWb  = sm + OFF_WB;
    float* sFW  = sm + OFF_FW;
    float* sFB  = sm + OFF_FB;

    const int tid  = threadIdx.x;
    const int lane = tid & 31;
    const int wid  = tid >> 5;
    const int col  = tid & 127;        // GEMM column
    const int kq   = tid >> 7;         // split-K quarter
    const int r    = blockIdx.x & 7;
    const int cid  = blockIdx.x >> 3;
    const int k    = lane;             // activation k (tid<128)
    const int b0   = wid * 2;          // activation batch pair (warps 0..3)
    const int b1   = b0 + 1;
    const uint32_t sbase = smem_u32(sm);

    float2 creg;

    for (int l = 0; l < LL; l++) {
        __syncthreads();  // previous-phase readers done (incl. post-loop y-warp)

        // ---- gather U slice transposed+padded: sU[col*260 + h] ----
        for (int idx = tid; idx < 4 * 256 * 32; idx += NTHR) {
            int g   = idx >> 13;
            int rem = idx & 8191;
            int h   = rem >> 5;
            int kl  = rem & 31;
            int kg  = r * 32 + kl;
            int hb  = h >> 6, n = h & 63;
            int cb  = kg >> 6, m = kg & 63;
            int sel = hb ^ cb;
            float sgn = ((QNEG_MASK >> (cb * 4 + hb)) & 1) ? -1.0f : 1.0f;
            const float* cp = (sel == 0) ? Ur : (sel == 1) ? Ui : (sel == 2) ? Uj : Uk;
            sU[(g * 32 + kl) * 260 + h] =
                sgn * __ldg(&cp[((l * 4 + g) * 64 + n) * 64 + m]);
        }
        for (int idx = tid; idx < 512; idx += NTHR) {
            int g  = idx >> 7;
            int f  = (idx >> 5) & 3;
            int kl = idx & 31;
            int kg = r * 32 + kl;
            int cb = kg >> 6, m = kg & 63;
            int sel = f ^ cb;
            float sgn = ((QNEG_MASK >> (cb * 4 + f)) & 1) ? -1.0f : 1.0f;
            const float* cp = (sel == 0) ? Wxr : (sel == 1) ? Wxi : (sel == 2) ? Wxj : Wxk;
            sWx[(g * 32 + kl) * 4 + f] = sgn * __ldg(&cp[(l * 4 + g) * 64 + m]);
        }
        for (int idx = tid; idx < 128; idx += NTHR) {
            int g = idx >> 5, kl = idx & 31;
            sWb[idx] = Wxb[(l * 4 + g) * 256 + r * 32 + kl];
        }
        for (int idx = tid; idx < 1024; idx += NTHR)
            sFW[idx] = fcw[l * 1024 + idx];            // [256 k][4 f]
        if (tid < 4) sFB[tid] = fcb[l * 4 + tid];
        // zero h buffer (h_0 = 0)
        for (int i = tid; i < 256 * 8; i += NTHR) sHB[i] = 0.0f;
        creg = make_float2(0.0f, 0.0f);

        cluster_sync();   // tables ready cluster-wide

        const float4* xp = (const float4*)((l == 0) ? x : g_y1);  // [B][T][4]

        for (int t = 0; t < TT; t++) {
            const float* hbc = sHB + kq * 512;         // kq*64 h × 8 b
            const float* up  = sU + col * 260 + kq * 64;

            // ---- y-warp: y_{t-1} = norm(fco(h_t)) (layer 0; overlaps GEMM) ----
            if (l == 0 && wid == 15 && t > 0) {
                float s0 = 0.f, s1 = 0.f, s2 = 0.f, s3 = 0.f;
#pragma unroll
                for (int i = 0; i < 8; i++) {
                    int kk = lane + i * 32;
                    float hv = sHB[kk * 8 + r];
                    float4 fw = *(const float4*)&sFW[kk * 4];
                    s0 += hv * fw.x; s1 += hv * fw.y;
                    s2 += hv * fw.z; s3 += hv * fw.w;
                }
#pragma unroll
                for (int m = 16; m >= 1; m >>= 1) {
                    s0 += __shfl_xor_sync(0xffffffffu, s0, m);
                    s1 += __shfl_xor_sync(0xffffffffu, s1, m);
                    s2 += __shfl_xor_sync(0xffffffffu, s2, m);
                    s3 += __shfl_xor_sync(0xffffffffu, s3, m);
                }
                if (lane == 0) {
                    s0 += sFB[0]; s1 += sFB[1]; s2 += sFB[2]; s3 += sFB[3];
                    float nn = s0 * s0 + s1 * s1 + s2 * s2 + s3 * s3;
                    float iv = 1.0f / fmaxf(sqrtf(nn), 1e-12f);
                    ((float4*)g_y1)[(cid * 8 + r) * TT + (t - 1)] =
                        make_float4(s0 * iv, s1 * iv, s2 * iv, s3 * iv);
                }
            }

            // ---- acc init: kq==0 adds bias + x_t @ Wx ----
            ull A0, A1, A2, A3;
            if (kq == 0) {
                float4 wxc = *(const float4*)&sWx[col * 4];
                float  wbc = sWb[col];
                float acc[8];
#pragma unroll
                for (int j = 0; j < 8; j++) {
                    float4 xv = __ldg(&xp[(cid * 8 + j) * TT + t]);
                    acc[j] = wbc + xv.x * wxc.x + xv.y * wxc.y
                                 + xv.z * wxc.z + xv.w * wxc.w;
                }
                A0 = pack2(acc[0], acc[1]); A1 = pack2(acc[2], acc[3]);
                A2 = pack2(acc[4], acc[5]); A3 = pack2(acc[6], acc[7]);
            } else {
                A0 = A1 = A2 = A3 = 0ull;
            }

            // ---- GEMM quarter: 64 h × 8 batches ----
#pragma unroll
            for (int hh = 0; hh < 64; hh += 4) {
                float4 u4 = *(const float4*)(up + hh);
                const float* hp = hbc + hh * 8;
                {
                    ull uu = pack2(u4.x, u4.x);
                    ulonglong2 a = *(const ulonglong2*)(hp);
                    ulonglong2 b = *(const ulonglong2*)(hp + 4);
                    A0 = ffma2(a.x, uu, A0); A1 = ffma2(a.y, uu, A1);
                    A2 = ffma2(b.x, uu, A2); A3 = ffma2(b.y, uu, A3);
                }
                {
                    ull uu = pack2(u4.y, u4.y);
                    ulonglong2 a = *(const ulonglong2*)(hp + 8);
                    ulonglong2 b = *(const ulonglong2*)(hp + 12);
                    A0 = ffma2(a.x, uu, A0); A1 = ffma2(a.y, uu, A1);
                    A2 = ffma2(b.x, uu, A2); A3 = ffma2(b.y, uu, A3);
                }
                {
                    ull uu = pack2(u4.z, u4.z);
                    ulonglong2 a = *(const ulonglong2*)(hp + 16);
                    ulonglong2 b = *(const ulonglong2*)(hp + 20);
                    A0 = ffma2(a.x, uu, A0); A1 = ffma2(a.y, uu, A1);
                    A2 = ffma2(b.x, uu, A2); A3 = ffma2(b.y, uu, A3);
                }
                {
                    ull uu = pack2(u4.w, u4.w);
                    ulonglong2 a = *(const ulonglong2*)(hp + 24);
                    ulonglong2 b = *(const ulonglong2*)(hp + 28);
                    A0 = ffma2(a.x, uu, A0); A1 = ffma2(a.y, uu, A1);
                    A2 = ffma2(b.x, uu, A2); A3 = ffma2(b.y, uu, A3);
                }
            }

            // ---- write partials: sPar[kq][b][col] (conflict-free STS.32) ----
            {
                float* pp = sPar + kq * 1024 + col;
                float2 v;
                v = unpack2(A0); pp[0 * 128] = v.x; pp[1 * 128] = v.y;
                v = unpack2(A1); pp[2 * 128] = v.x; pp[3 * 128] = v.y;
                v = unpack2(A2); pp[4 * 128] = v.x; pp[5 * 128] = v.y;
                v = unpack2(A3); pp[6 * 128] = v.x; pp[7 * 128] = v.y;
            }
            __syncthreads();

            // ---- combine + activations + LOCAL h store (tid<128) ----
            if (tid < 128) {
                float hn0, hn1;
#pragma unroll
                for (int bi = 0; bi < 2; bi++) {
                    const int b = bi ? b1 : b0;
                    const float* pb = sPar + b * 128 + k;
                    float pf = 0.f, pi = 0.f, po = 0.f, pc = 0.f;
#pragma unroll
                    for (int q = 0; q < 4; q++) {
                        const float* pq = pb + q * 1024;
                        pf += pq[0];
                        pi += pq[32];
                        po += pq[64];
                        pc += pq[96];
                    }
                    float ft = fsig(pf);
                    float it = fsig(pi);
                    float ot = fsig(po);
                    float ct = ftanh(pc);
                    float cold = bi ? creg.y : creg.x;
                    float c  = it * ct + ft * cold;
                    if (bi) creg.y = c; else creg.x = c;
                    float hn = ot * ftanh(c);
                    if (bi) hn1 = hn; else hn0 = hn;
                }
                // local store of this CTA's slice (parity double-buffer)
                *(ull*)(sOut + (t & 1) * 256 + k * 8 + b0) = pack2(hn0, hn1);
            }

            cluster_sync();   // slices published; only local STS to drain

            // ---- pull all 8 slices into local sHB (remote DSMEM reads) ----
            {
                const uint32_t so = sbase + (OFF_OUT + (t & 1) * 256) * 4;
#pragma unroll
                for (int i = tid; i < 1024; i += NTHR) {
                    int j   = i >> 7;        // source rank
                    int off = i & 127;       // b64 index in slice
                    uint32_t ra;
                    asm("mapa.shared::cluster.u32 %0, %1, %2;"
                        : "=r"(ra) : "r"(so + off * 8), "r"(j));
                    ull v;
                    asm volatile("ld.shared::cluster.b64 %0, [%1];"
                                 : "=l"(v) : "r"(ra) : "memory");
                    *(ull*)(sHB + j * 256 + off * 2) = v;
                }
            }
            __syncthreads();  // sHB = h_{t+1} complete
        } // t

        // ---- final y from h_T (both layers), overl. nothing: once per layer ----
        if (wid == 15) {
            float s0 = 0.f, s1 = 0.f, s2 = 0.f, s3 = 0.f;
#pragma unroll
            for (int i = 0; i < 8; i++) {
                int kk = lane + i * 32;
                float hv = sHB[kk * 8 + r];
                float4 fw = *(const float4*)&sFW[kk * 4];
                s0 += hv * fw.x; s1 += hv * fw.y;
                s2 += hv * fw.z; s3 += hv * fw.w;
            }
#pragma unroll
            for (int m = 16; m >= 1; m >>= 1) {
                s0 += __shfl_xor_sync(0xffffffffu, s0, m);
                s1 += __shfl_xor_sync(0xffffffffu, s1, m);
                s2 += __shfl_xor_sync(0xffffffffu, s2, m);
                s3 += __shfl_xor_sync(0xffffffffu, s3, m);
            }
            if (lane == 0) {
                s0 += sFB[0]; s1 += sFB[1]; s2 += sFB[2]; s3 += sFB[3];
                float nn = s0 * s0 + s1 * s1 + s2 * s2 + s3 * s3;
                float iv = 1.0f / fmaxf(sqrtf(nn), 1e-12f);
                if (l == 0) {
                    ((float4*)g_y1)[(cid * 8 + r) * TT + (TT - 1)] =
                        make_float4(s0 * iv, s1 * iv, s2 * iv, s3 * iv);
                } else {
                    ((float4*)out)[cid * 8 + r] =
                        make_float4(s0 * iv, s1 * iv, s2 * iv, s3 * iv);
                }
            }
        }
    } // l
}

extern "C" void kernel_launch(void* const* d_in, const int* in_sizes, int n_in,
                              void* d_out, int out_size)
{
    (void)in_sizes; (void)n_in; (void)out_size;
    cudaFuncSetAttribute(qlstm_kernel,
                         cudaFuncAttributeMaxDynamicSharedMemorySize, SMEM_BYTES);
    qlstm_kernel<<<NCL * CLSZ, NTHR, SMEM_BYTES>>>(
        (const float*)d_in[0],
        (const float*)d_in[1], (const float*)d_in[2],
        (const float*)d_in[3], (const float*)d_in[4],
        (const float*)d_in[5],
        (const float*)d_in[6], (const float*)d_in[7],
        (const float*)d_in[8], (const float*)d_in[9],
        (const float*)d_in[10], (const float*)d_in[11],
        (float*)d_out);
}

// round 7
// speedup vs baseline: 1.9231x; 1.0385x over previous
#include <cuda_runtime.h>
#include <cstdint>

#define LL   2
#define TT   512
#define BB   128
#define HH   256
#define CLSZ 8
#define NCL  16
#define NTHR 512

// ---------------- smem layout (float indices) ----------------
#define OFF_U    0          // [128 col][260 pad h]         33280
#define OFF_HB   33280      // [256 h][8 b]                  2048
#define OFF_OUT  35328      // [2 parity][32 k][8 b]          512
#define OFF_PAR  35840      // [4 kq][8 b][128 col]          4096
#define OFF_WX   39936      // [128 col][4 f]                 512
#define OFF_WB   40448      // [128 col]                      128
#define OFF_FW   40576      // [256 k][4 f]                  1024
#define OFF_FB   41600      // [4]                              4
#define OFF_FLAG 41604      // [8] int step flags              8
#define SMEM_FLOATS 41612
#define SMEM_BYTES (SMEM_FLOATS * 4)

// layer-1 output scratch, TRANSPOSED: [B][T][4]
__device__ float g_y1[BB * TT * 4];

typedef unsigned long long ull;

__device__ __forceinline__ uint32_t smem_u32(const void* p) {
    uint32_t a;
    asm("{ .reg .u64 t; cvta.to.shared.u64 t, %1; cvt.u32.u64 %0, t; }"
        : "=r"(a) : "l"(p));
    return a;
}
__device__ __forceinline__ void cluster_sync() {
    asm volatile("barrier.cluster.arrive.aligned;" ::: "memory");
    asm volatile("barrier.cluster.wait.aligned;" ::: "memory");
}
__device__ __forceinline__ ull pack2(float a, float b) {
    ull r; asm("mov.b64 %0, {%1, %2};" : "=l"(r) : "f"(a), "f"(b)); return r;
}
__device__ __forceinline__ float2 unpack2(ull v) {
    float2 r; asm("mov.b64 {%0, %1}, %2;" : "=f"(r.x), "=f"(r.y) : "l"(v)); return r;
}
__device__ __forceinline__ ull ffma2(ull a, ull b, ull c) {
    ull d; asm("fma.rn.f32x2 %0, %1, %2, %3;" : "=l"(d) : "l"(a), "l"(b), "l"(c)); return d;
}
__device__ __forceinline__ float fsig(float x) {
    float e, r;
    asm("ex2.approx.f32 %0, %1;" : "=f"(e) : "f"(x * -1.4426950408889634f));
    asm("rcp.approx.f32 %0, %1;" : "=f"(r) : "f"(1.0f + e));
    return r;
}
__device__ __forceinline__ float ftanh(float x) {
    float e, r;
    asm("ex2.approx.f32 %0, %1;" : "=f"(e) : "f"(x * -2.8853900817779268f));
    asm("rcp.approx.f32 %0, %1;" : "=f"(r) : "f"(1.0f + e));
    return __fmaf_rn(2.0f, r, -1.0f);
}
// spin until local flag word >= target (peer writes via st.shared::cluster)
__device__ __forceinline__ void flag_spin(uint32_t fa, int target) {
    int v;
    do {
        asm volatile("ld.volatile.shared.b32 %0, [%1];" : "=r"(v) : "r"(fa));
    } while (v < target);
}

#define QNEG_MASK 0x284E

__global__ void __launch_bounds__(NTHR, 1) __cluster_dims__(CLSZ, 1, 1)
qlstm_kernel(const float* __restrict__ x,
             const float* __restrict__ Wxr, const float* __restrict__ Wxi,
             const float* __restrict__ Wxj, const float* __restrict__ Wxk,
             const float* __restrict__ Wxb,
             const float* __restrict__ Ur,  const float* __restrict__ Ui,
             const float* __restrict__ Uj,  const float* __restrict__ Uk,
             const float* __restrict__ fcw, const float* __restrict__ fcb,
             float* __restrict__ out)
{
    extern __shared__ float sm[];
    float* sU   = sm + OFF_U;
    float* sHB  = sm + OFF_HB;
    float* sOut = sm + OFF_OUT;
    float* sPar = sm + OFF_PAR;
    float* sWx  = sm + OFF_WX;
    float* sWb  = sm + OFF_WB;
    float* sFW  = sm + OFF_FW;
    float* sFB  = sm + OFF_FB;

    const int tid  = threadIdx.x;
    const int lane = tid & 31;
    const int wid  = tid >> 5;
    const int col  = tid & 127;        // GEMM column
    const int kq   = tid >> 7;         // split-K quarter
    const int r    = blockIdx.x & 7;
    const int cid  = blockIdx.x >> 3;
    const int k    = lane;             // activation k (tid<128)
    const int b0   = wid * 2;          // activation batch pair (warps 0..3)
    const int b1   = b0 + 1;
    const uint32_t sbase = smem_u32(sm);

    // pull-plan: thread handles (rank j0, off) and (rank j0+4, off)
    const int poff = tid & 127;        // b64 index within slice
    const int j0   = tid >> 7;         // 0..3
    const int j1   = j0 + 4;
    const uint32_t flag0 = sbase + (OFF_FLAG + j0) * 4;
    const uint32_t flag1 = sbase + (OFF_FLAG + j1) * 4;

    // ---- one-time init ----
    if (tid < 8) ((int*)(sm + OFF_FLAG))[tid] = 0;
    __syncthreads();
    cluster_sync();    // flags zeroed cluster-wide before any flag can arrive

    float2 creg;

    for (int l = 0; l < LL; l++) {
        __syncthreads();  // previous-phase readers done (incl. post-loop y-warp)

        // ---- gather U slice transposed+padded: sU[col*260 + h] ----
        for (int idx = tid; idx < 4 * 256 * 32; idx += NTHR) {
            int g   = idx >> 13;
            int rem = idx & 8191;
            int h   = rem >> 5;
            int kl  = rem & 31;
            int kg  = r * 32 + kl;
            int hb  = h >> 6, n = h & 63;
            int cb  = kg >> 6, m = kg & 63;
            int sel = hb ^ cb;
            float sgn = ((QNEG_MASK >> (cb * 4 + hb)) & 1) ? -1.0f : 1.0f;
            const float* cp = (sel == 0) ? Ur : (sel == 1) ? Ui : (sel == 2) ? Uj : Uk;
            sU[(g * 32 + kl) * 260 + h] =
                sgn * __ldg(&cp[((l * 4 + g) * 64 + n) * 64 + m]);
        }
        for (int idx = tid; idx < 512; idx += NTHR) {
            int g  = idx >> 7;
            int f  = (idx >> 5) & 3;
            int kl = idx & 31;
            int kg = r * 32 + kl;
            int cb = kg >> 6, m = kg & 63;
            int sel = f ^ cb;
            float sgn = ((QNEG_MASK >> (cb * 4 + f)) & 1) ? -1.0f : 1.0f;
            const float* cp = (sel == 0) ? Wxr : (sel == 1) ? Wxi : (sel == 2) ? Wxj : Wxk;
            sWx[(g * 32 + kl) * 4 + f] = sgn * __ldg(&cp[(l * 4 + g) * 64 + m]);
        }
        for (int idx = tid; idx < 128; idx += NTHR) {
            int g = idx >> 5, kl = idx & 31;
            sWb[idx] = Wxb[(l * 4 + g) * 256 + r * 32 + kl];
        }
        for (int idx = tid; idx < 1024; idx += NTHR)
            sFW[idx] = fcw[l * 1024 + idx];            // [256 k][4 f]
        if (tid < 4) sFB[tid] = fcb[l * 4 + tid];
        // zero h buffer (h_0 = 0); purely local — no cluster barrier needed
        for (int i = tid; i < 256 * 8; i += NTHR) sHB[i] = 0.0f;
        creg = make_float2(0.0f, 0.0f);
        __syncthreads();

        const float4* xp = (const float4*)((l == 0) ? x : g_y1);  // [B][T][4]

        for (int t = 0; t < TT; t++) {
            const float* hbc = sHB + kq * 512;         // kq*64 h × 8 b
            const float* up  = sU + col * 260 + kq * 64;

            // ---- y-warp: y_{t-1} = norm(fco(h_t)) (layer 0; overlaps GEMM) ----
            if (l == 0 && wid == 15 && t > 0) {
                float s0 = 0.f, s1 = 0.f, s2 = 0.f, s3 = 0.f;
#pragma unroll
                for (int i = 0; i < 8; i++) {
                    int kk = lane + i * 32;
                    float hv = sHB[kk * 8 + r];
                    float4 fw = *(const float4*)&sFW[kk * 4];
                    s0 += hv * fw.x; s1 += hv * fw.y;
                    s2 += hv * fw.z; s3 += hv * fw.w;
                }
#pragma unroll
                for (int m = 16; m >= 1; m >>= 1) {
                    s0 += __shfl_xor_sync(0xffffffffu, s0, m);
                    s1 += __shfl_xor_sync(0xffffffffu, s1, m);
                    s2 += __shfl_xor_sync(0xffffffffu, s2, m);
                    s3 += __shfl_xor_sync(0xffffffffu, s3, m);
                }
                if (lane == 0) {
                    s0 += sFB[0]; s1 += sFB[1]; s2 += sFB[2]; s3 += sFB[3];
                    float nn = s0 * s0 + s1 * s1 + s2 * s2 + s3 * s3;
                    float iv = 1.0f / fmaxf(sqrtf(nn), 1e-12f);
                    ((float4*)g_y1)[(cid * 8 + r) * TT + (t - 1)] =
                        make_float4(s0 * iv, s1 * iv, s2 * iv, s3 * iv);
                }
            }

            // ---- acc init: kq==0 adds bias + x_t @ Wx ----
            ull A0, A1, A2, A3;
            if (kq == 0) {
                float4 wxc = *(const float4*)&sWx[col * 4];
                float  wbc = sWb[col];
                float acc[8];
#pragma unroll
                for (int j = 0; j < 8; j++) {
                    float4 xv = __ldg(&xp[(cid * 8 + j) * TT + t]);
                    acc[j] = wbc + xv.x * wxc.x + xv.y * wxc.y
                                 + xv.z * wxc.z + xv.w * wxc.w;
                }
                A0 = pack2(acc[0], acc[1]); A1 = pack2(acc[2], acc[3]);
                A2 = pack2(acc[4], acc[5]); A3 = pack2(acc[6], acc[7]);
            } else {
                A0 = A1 = A2 = A3 = 0ull;
            }

            // ---- GEMM quarter: 64 h × 8 batches ----
#pragma unroll
            for (int hh = 0; hh < 64; hh += 4) {
                float4 u4 = *(const float4*)(up + hh);
                const float* hp = hbc + hh * 8;
                {
                    ull uu = pack2(u4.x, u4.x);
                    ulonglong2 a = *(const ulonglong2*)(hp);
                    ulonglong2 b = *(const ulonglong2*)(hp + 4);
                    A0 = ffma2(a.x, uu, A0); A1 = ffma2(a.y, uu, A1);
                    A2 = ffma2(b.x, uu, A2); A3 = ffma2(b.y, uu, A3);
                }
                {
                    ull uu = pack2(u4.y, u4.y);
                    ulonglong2 a = *(const ulonglong2*)(hp + 8);
                    ulonglong2 b = *(const ulonglong2*)(hp + 12);
                    A0 = ffma2(a.x, uu, A0); A1 = ffma2(a.y, uu, A1);
                    A2 = ffma2(b.x, uu, A2); A3 = ffma2(b.y, uu, A3);
                }
                {
                    ull uu = pack2(u4.z, u4.z);
                    ulonglong2 a = *(const ulonglong2*)(hp + 16);
                    ulonglong2 b = *(const ulonglong2*)(hp + 20);
                    A0 = ffma2(a.x, uu, A0); A1 = ffma2(a.y, uu, A1);
                    A2 = ffma2(b.x, uu, A2); A3 = ffma2(b.y, uu, A3);
                }
                {
                    ull uu = pack2(u4.w, u4.w);
                    ulonglong2 a = *(const ulonglong2*)(hp + 24);
                    ulonglong2 b = *(const ulonglong2*)(hp + 28);
                    A0 = ffma2(a.x, uu, A0); A1 = ffma2(a.y, uu, A1);
                    A2 = ffma2(b.x, uu, A2); A3 = ffma2(b.y, uu, A3);
                }
            }

            // ---- write partials: sPar[kq][b][col] ----
            {
                float* pp = sPar + kq * 1024 + col;
                float2 v;
                v = unpack2(A0); pp[0 * 128] = v.x; pp[1 * 128] = v.y;
                v = unpack2(A1); pp[2 * 128] = v.x; pp[3 * 128] = v.y;
                v = unpack2(A2); pp[4 * 128] = v.x; pp[5 * 128] = v.y;
                v = unpack2(A3); pp[6 * 128] = v.x; pp[7 * 128] = v.y;
            }
            __syncthreads();

            // ---- combine + activations + LOCAL h store (tid<128) ----
            if (tid < 128) {
                float hn0, hn1;
#pragma unroll
                for (int bi = 0; bi < 2; bi++) {
                    const int b = bi ? b1 : b0;
                    const float* pb = sPar + b * 128 + k;
                    float pf = 0.f, pi = 0.f, po = 0.f, pc = 0.f;
#pragma unroll
                    for (int q = 0; q < 4; q++) {
                        const float* pq = pb + q * 1024;
                        pf += pq[0];
                        pi += pq[32];
                        po += pq[64];
                        pc += pq[96];
                    }
                    float ft = fsig(pf);
                    float it = fsig(pi);
                    float ot = fsig(po);
                    float ct = ftanh(pc);
                    float cold = bi ? creg.y : creg.x;
                    float c  = it * ct + ft * cold;
                    if (bi) creg.y = c; else creg.x = c;
                    float hn = ot * ftanh(c);
                    if (bi) hn1 = hn; else hn0 = hn;
                }
                *(ull*)(sOut + (t & 1) * 256 + k * 8 + b0) = pack2(hn0, hn1);
            }

            __syncthreads();   // drains sOut STS to SMEM (HW-native on BAR)

            // ---- publish: push step flag to all 8 ranks (monotonic, no ABA) ----
            const int gs = l * TT + t + 1;
            if (tid == 0) {
                uint32_t fa = sbase + (OFF_FLAG + r) * 4;
#pragma unroll
                for (int j = 0; j < CLSZ; j++) {
                    uint32_t ra;
                    asm("mapa.shared::cluster.u32 %0, %1, %2;"
                        : "=r"(ra) : "r"(fa), "r"(j));
                    asm volatile("st.shared::cluster.b32 [%0], %1;"
                                 :: "r"(ra), "r"(gs) : "memory");
                }
            }

            // ---- spin on the 2 source ranks this thread pulls from ----
            flag_spin(flag0, gs);
            flag_spin(flag1, gs);

            // ---- pull both slices into local sHB ----
            {
                const uint32_t so = sbase + (OFF_OUT + (t & 1) * 256) * 4 + poff * 8;
                uint32_t ra; ull v;
                asm("mapa.shared::cluster.u32 %0, %1, %2;"
                    : "=r"(ra) : "r"(so), "r"(j0));
                asm volatile("ld.shared::cluster.b64 %0, [%1];"
                             : "=l"(v) : "r"(ra) : "memory");
                *(ull*)(sHB + j0 * 256 + poff * 2) = v;
                asm("mapa.shared::cluster.u32 %0, %1, %2;"
                    : "=r"(ra) : "r"(so), "r"(j1));
                asm volatile("ld.shared::cluster.b64 %0, [%1];"
                             : "=l"(v) : "r"(ra) : "memory");
                *(ull*)(sHB + j1 * 256 + poff * 2) = v;
            }
            __syncthreads();  // sHB = h_{t+1} complete
        } // t

        // ---- final y from h_T (both layers) ----
        if (wid == 15) {
            float s0 = 0.f, s1 = 0.f, s2 = 0.f, s3 = 0.f;
#pragma unroll
            for (int i = 0; i < 8; i++) {
                int kk = lane + i * 32;
                float hv = sHB[kk * 8 + r];
                float4 fw = *(const float4*)&sFW[kk * 4];
                s0 += hv * fw.x; s1 += hv * fw.y;
                s2 += hv * fw.z; s3 += hv * fw.w;
            }
#pragma unroll
            for (int m = 16; m >= 1; m >>= 1) {
                s0 += __shfl_xor_sync(0xffffffffu, s0, m);
                s1 += __shfl_xor_sync(0xffffffffu, s1, m);
                s2 += __shfl_xor_sync(0xffffffffu, s2, m);
                s3 += __shfl_xor_sync(0xffffffffu, s3, m);
            }
            if (lane == 0) {
                s0 += sFB[0]; s1 += sFB[1]; s2 += sFB[2]; s3 += sFB[3];
                float nn = s0 * s0 + s1 * s1 + s2 * s2 + s3 * s3;
                float iv = 1.0f / fmaxf(sqrtf(nn), 1e-12f);
                if (l == 0) {
                    ((float4*)g_y1)[(cid * 8 + r) * TT + (TT - 1)] =
                        make_float4(s0 * iv, s1 * iv, s2 * iv, s3 * iv);
                } else {
                    ((float4*)out)[cid * 8 + r] =
                        make_float4(s0 * iv, s1 * iv, s2 * iv, s3 * iv);
                }
            }
        }
    } // l

    cluster_sync();   // no CTA exits while peers may still touch its SMEM
}

extern "C" void kernel_launch(void* const* d_in, const int* in_sizes, int n_in,
                              void* d_out, int out_size)
{
    (void)in_sizes; (void)n_in; (void)out_size;
    cudaFuncSetAttribute(qlstm_kernel,
                         cudaFuncAttributeMaxDynamicSharedMemorySize, SMEM_BYTES);
    qlstm_kernel<<<NCL * CLSZ, NTHR, SMEM_BYTES>>>(
        (const float*)d_in[0],
        (const float*)d_in[1], (const float*)d_in[2],
        (const float*)d_in[3], (const float*)d_in[4],
        (const float*)d_in[5],
        (const float*)d_in[6], (const float*)d_in[7],
        (const float*)d_in[8], (const float*)d_in[9],
        (const float*)d_in[10], (const float*)d_in[11],
        (float*)d_out);
}

// round 8
// speedup vs baseline: 1.9235x; 1.0002x over previous
#include <cuda_runtime.h>
#include <cstdint>

#define LL   2
#define TT   512
#define BB   128
#define HH   256
#define CLSZ 8
#define NCL  16
#define NTHR 512

// ---------------- smem layout (float indices) ----------------
#define OFF_U    0          // [128 col][260 pad h]         33280
#define OFF_HB   33280      // [256 h][8 b]                  2048
#define OFF_OUT  35328      // [2 parity][32 k][8 b]          512
#define OFF_PAR  35840      // [4 kq][8 b][128 col]          4096
#define OFF_WX   39936      // [128 col][4 f]                 512
#define OFF_WB   40448      // [128 col]                      128
#define OFF_FW   40576      // [256 k][4 f]                  1024
#define OFF_FB   41600      // [4]                              4
#define OFF_FLAG 41604      // [8] int step flags              8
#define SMEM_FLOATS 41612
#define SMEM_BYTES (SMEM_FLOATS * 4)

// layer-1 output scratch, TRANSPOSED: [B][T][4]
__device__ float g_y1[BB * TT * 4];

typedef unsigned long long ull;

__device__ __forceinline__ uint32_t smem_u32(const void* p) {
    uint32_t a;
    asm("{ .reg .u64 t; cvta.to.shared.u64 t, %1; cvt.u32.u64 %0, t; }"
        : "=r"(a) : "l"(p));
    return a;
}
__device__ __forceinline__ void cluster_sync() {
    asm volatile("barrier.cluster.arrive.aligned;" ::: "memory");
    asm volatile("barrier.cluster.wait.aligned;" ::: "memory");
}
__device__ __forceinline__ ull pack2(float a, float b) {
    ull r; asm("mov.b64 %0, {%1, %2};" : "=l"(r) : "f"(a), "f"(b)); return r;
}
__device__ __forceinline__ float2 unpack2(ull v) {
    float2 r; asm("mov.b64 {%0, %1}, %2;" : "=f"(r.x), "=f"(r.y) : "l"(v)); return r;
}
__device__ __forceinline__ ull ffma2(ull a, ull b, ull c) {
    ull d; asm("fma.rn.f32x2 %0, %1, %2, %3;" : "=l"(d) : "l"(a), "l"(b), "l"(c)); return d;
}
__device__ __forceinline__ float fsig(float x) {
    float e, r;
    asm("ex2.approx.f32 %0, %1;" : "=f"(e) : "f"(x * -1.4426950408889634f));
    asm("rcp.approx.f32 %0, %1;" : "=f"(r) : "f"(1.0f + e));
    return r;
}
__device__ __forceinline__ float ftanh(float x) {
    float e, r;
    asm("ex2.approx.f32 %0, %1;" : "=f"(e) : "f"(x * -2.8853900817779268f));
    asm("rcp.approx.f32 %0, %1;" : "=f"(r) : "f"(1.0f + e));
    return __fmaf_rn(2.0f, r, -1.0f);
}
// spin until local flag word >= target (peer writes via st.shared::cluster)
__device__ __forceinline__ void flag_spin(uint32_t fa, int target) {
    int v;
    do {
        asm volatile("ld.volatile.shared.b32 %0, [%1];" : "=r"(v) : "r"(fa));
    } while (v < target);
}

#define QNEG_MASK 0x284E

__global__ void __launch_bounds__(NTHR, 1) __cluster_dims__(CLSZ, 1, 1)
qlstm_kernel(const float* __restrict__ x,
             const float* __restrict__ Wxr, const float* __restrict__ Wxi,
             const float* __restrict__ Wxj, const float* __restrict__ Wxk,
             const float* __restrict__ Wxb,
             const float* __restrict__ Ur,  const float* __restrict__ Ui,
             const float* __restrict__ Uj,  const float* __restrict__ Uk,
             const float* __restrict__ fcw, const float* __restrict__ fcb,
             float* __restrict__ out)
{
    extern __shared__ float sm[];
    float* sU   = sm + OFF_U;
    float* sHB  = sm + OFF_HB;
    float* sOut = sm + OFF_OUT;
    float* sPar = sm + OFF_PAR;
    float* sWx  = sm + OFF_WX;
    float* sWb  = sm + OFF_WB;
    float* sFW  = sm + OFF_FW;
    float* sFB  = sm + OFF_FB;

    const int tid  = threadIdx.x;
    const int lane = tid & 31;
    const int wid  = tid >> 5;
    const int col  = tid & 127;        // GEMM column
    const int kq   = tid >> 7;         // split-K quarter
    const int r    = blockIdx.x & 7;
    const int cid  = blockIdx.x >> 3;
    const int k    = lane;             // activation k (tid<128)
    const int b0   = wid * 2;          // activation batch pair (warps 0..3)
    const int b1   = b0 + 1;
    const uint32_t sbase = smem_u32(sm);

    // pull-plan: thread handles (rank j0, off) and (rank j0+4, off)
    const int poff = tid & 127;        // b64 index within slice
    const int j0   = tid >> 7;         // 0..3
    const int j1   = j0 + 4;
    const uint32_t flag0 = sbase + (OFF_FLAG + j0) * 4;
    const uint32_t flag1 = sbase + (OFF_FLAG + j1) * 4;

    // ---- one-time init ----
    if (tid < 8) ((int*)(sm + OFF_FLAG))[tid] = 0;
    __syncthreads();
    cluster_sync();    // flags zeroed cluster-wide before any flag can arrive

    float2 creg;

    for (int l = 0; l < LL; l++) {
        __syncthreads();  // previous-phase readers done (incl. post-loop y-warp)

        // ---- gather U slice transposed+padded: sU[col*260 + h] ----
        for (int idx = tid; idx < 4 * 256 * 32; idx += NTHR) {
            int g   = idx >> 13;
            int rem = idx & 8191;
            int h   = rem >> 5;
            int kl  = rem & 31;
            int kg  = r * 32 + kl;
            int hb  = h >> 6, n = h & 63;
            int cb  = kg >> 6, m = kg & 63;
            int sel = hb ^ cb;
            float sgn = ((QNEG_MASK >> (cb * 4 + hb)) & 1) ? -1.0f : 1.0f;
            const float* cp = (sel == 0) ? Ur : (sel == 1) ? Ui : (sel == 2) ? Uj : Uk;
            sU[(g * 32 + kl) * 260 + h] =
                sgn * __ldg(&cp[((l * 4 + g) * 64 + n) * 64 + m]);
        }
        for (int idx = tid; idx < 512; idx += NTHR) {
            int g  = idx >> 7;
            int f  = (idx >> 5) & 3;
            int kl = idx & 31;
            int kg = r * 32 + kl;
            int cb = kg >> 6, m = kg & 63;
            int sel = f ^ cb;
            float sgn = ((QNEG_MASK >> (cb * 4 + f)) & 1) ? -1.0f : 1.0f;
            const float* cp = (sel == 0) ? Wxr : (sel == 1) ? Wxi : (sel == 2) ? Wxj : Wxk;
            sWx[(g * 32 + kl) * 4 + f] = sgn * __ldg(&cp[(l * 4 + g) * 64 + m]);
        }
        for (int idx = tid; idx < 128; idx += NTHR) {
            int g = idx >> 5, kl = idx & 31;
            sWb[idx] = Wxb[(l * 4 + g) * 256 + r * 32 + kl];
        }
        for (int idx = tid; idx < 1024; idx += NTHR)
            sFW[idx] = fcw[l * 1024 + idx];            // [256 k][4 f]
        if (tid < 4) sFB[tid] = fcb[l * 4 + tid];
        // zero h buffer (h_0 = 0); purely local — no cluster barrier needed
        for (int i = tid; i < 256 * 8; i += NTHR) sHB[i] = 0.0f;
        creg = make_float2(0.0f, 0.0f);
        __syncthreads();

        const float4* xp = (const float4*)((l == 0) ? x : g_y1);  // [B][T][4]

        for (int t = 0; t < TT; t++) {
            const float* hbc = sHB + kq * 512;         // kq*64 h × 8 b
            const float* up  = sU + col * 260 + kq * 64;

            // ---- y-warp: y_{t-1} = norm(fco(h_t)) (layer 0; overlaps GEMM) ----
            if (l == 0 && wid == 15 && t > 0) {
                float s0 = 0.f, s1 = 0.f, s2 = 0.f, s3 = 0.f;
#pragma unroll
                for (int i = 0; i < 8; i++) {
                    int kk = lane + i * 32;
                    float hv = sHB[kk * 8 + r];
                    float4 fw = *(const float4*)&sFW[kk * 4];
                    s0 += hv * fw.x; s1 += hv * fw.y;
                    s2 += hv * fw.z; s3 += hv * fw.w;
                }
#pragma unroll
                for (int m = 16; m >= 1; m >>= 1) {
                    s0 += __shfl_xor_sync(0xffffffffu, s0, m);
                    s1 += __shfl_xor_sync(0xffffffffu, s1, m);
                    s2 += __shfl_xor_sync(0xffffffffu, s2, m);
                    s3 += __shfl_xor_sync(0xffffffffu, s3, m);
                }
                if (lane == 0) {
                    s0 += sFB[0]; s1 += sFB[1]; s2 += sFB[2]; s3 += sFB[3];
                    float nn = s0 * s0 + s1 * s1 + s2 * s2 + s3 * s3;
                    float iv = 1.0f / fmaxf(sqrtf(nn), 1e-12f);
                    ((float4*)g_y1)[(cid * 8 + r) * TT + (t - 1)] =
                        make_float4(s0 * iv, s1 * iv, s2 * iv, s3 * iv);
                }
            }

            // ---- acc init: kq==0 adds bias + x_t @ Wx ----
            ull A0, A1, A2, A3;
            if (kq == 0) {
                float4 wxc = *(const float4*)&sWx[col * 4];
                float  wbc = sWb[col];
                float acc[8];
#pragma unroll
                for (int j = 0; j < 8; j++) {
                    float4 xv = __ldg(&xp[(cid * 8 + j) * TT + t]);
                    acc[j] = wbc + xv.x * wxc.x + xv.y * wxc.y
                                 + xv.z * wxc.z + xv.w * wxc.w;
                }
                A0 = pack2(acc[0], acc[1]); A1 = pack2(acc[2], acc[3]);
                A2 = pack2(acc[4], acc[5]); A3 = pack2(acc[6], acc[7]);
            } else {
                A0 = A1 = A2 = A3 = 0ull;
            }

            // ---- GEMM quarter: 64 h × 8 batches ----
#pragma unroll
            for (int hh = 0; hh < 64; hh += 4) {
                float4 u4 = *(const float4*)(up + hh);
                const float* hp = hbc + hh * 8;
                {
                    ull uu = pack2(u4.x, u4.x);
                    ulonglong2 a = *(const ulonglong2*)(hp);
                    ulonglong2 b = *(const ulonglong2*)(hp + 4);
                    A0 = ffma2(a.x, uu, A0); A1 = ffma2(a.y, uu, A1);
                    A2 = ffma2(b.x, uu, A2); A3 = ffma2(b.y, uu, A3);
                }
                {
                    ull uu = pack2(u4.y, u4.y);
                    ulonglong2 a = *(const ulonglong2*)(hp + 8);
                    ulonglong2 b = *(const ulonglong2*)(hp + 12);
                    A0 = ffma2(a.x, uu, A0); A1 = ffma2(a.y, uu, A1);
                    A2 = ffma2(b.x, uu, A2); A3 = ffma2(b.y, uu, A3);
                }
                {
                    ull uu = pack2(u4.z, u4.z);
                    ulonglong2 a = *(const ulonglong2*)(hp + 16);
                    ulonglong2 b = *(const ulonglong2*)(hp + 20);
                    A0 = ffma2(a.x, uu, A0); A1 = ffma2(a.y, uu, A1);
                    A2 = ffma2(b.x, uu, A2); A3 = ffma2(b.y, uu, A3);
                }
                {
                    ull uu = pack2(u4.w, u4.w);
                    ulonglong2 a = *(const ulonglong2*)(hp + 24);
                    ulonglong2 b = *(const ulonglong2*)(hp + 28);
                    A0 = ffma2(a.x, uu, A0); A1 = ffma2(a.y, uu, A1);
                    A2 = ffma2(b.x, uu, A2); A3 = ffma2(b.y, uu, A3);
                }
            }

            // ---- write partials: sPar[kq][b][col] ----
            {
                float* pp = sPar + kq * 1024 + col;
                float2 v;
                v = unpack2(A0); pp[0 * 128] = v.x; pp[1 * 128] = v.y;
                v = unpack2(A1); pp[2 * 128] = v.x; pp[3 * 128] = v.y;
                v = unpack2(A2); pp[4 * 128] = v.x; pp[5 * 128] = v.y;
                v = unpack2(A3); pp[6 * 128] = v.x; pp[7 * 128] = v.y;
            }
            __syncthreads();

            // ---- combine + activations + LOCAL h store (tid<128) ----
            if (tid < 128) {
                float hn0, hn1;
#pragma unroll
                for (int bi = 0; bi < 2; bi++) {
                    const int b = bi ? b1 : b0;
                    const float* pb = sPar + b * 128 + k;
                    float pf = 0.f, pi = 0.f, po = 0.f, pc = 0.f;
#pragma unroll
                    for (int q = 0; q < 4; q++) {
                        const float* pq = pb + q * 1024;
                        pf += pq[0];
                        pi += pq[32];
                        po += pq[64];
                        pc += pq[96];
                    }
                    float ft = fsig(pf);
                    float it = fsig(pi);
                    float ot = fsig(po);
                    float ct = ftanh(pc);
                    float cold = bi ? creg.y : creg.x;
                    float c  = it * ct + ft * cold;
                    if (bi) creg.y = c; else creg.x = c;
                    float hn = ot * ftanh(c);
                    if (bi) hn1 = hn; else hn0 = hn;
                }
                *(ull*)(sOut + (t & 1) * 256 + k * 8 + b0) = pack2(hn0, hn1);
            }

            __syncthreads();   // drains sOut STS to SMEM (HW-native on BAR)

            // ---- publish: push step flag to all 8 ranks (monotonic, no ABA) ----
            const int gs = l * TT + t + 1;
            if (tid == 0) {
                uint32_t fa = sbase + (OFF_FLAG + r) * 4;
#pragma unroll
                for (int j = 0; j < CLSZ; j++) {
                    uint32_t ra;
                    asm("mapa.shared::cluster.u32 %0, %1, %2;"
                        : "=r"(ra) : "r"(fa), "r"(j));
                    asm volatile("st.shared::cluster.b32 [%0], %1;"
                                 :: "r"(ra), "r"(gs) : "memory");
                }
            }

            // ---- spin on the 2 source ranks this thread pulls from ----
            flag_spin(flag0, gs);
            flag_spin(flag1, gs);

            // ---- pull both slices into local sHB ----
            {
                const uint32_t so = sbase + (OFF_OUT + (t & 1) * 256) * 4 + poff * 8;
                uint32_t ra; ull v;
                asm("mapa.shared::cluster.u32 %0, %1, %2;"
                    : "=r"(ra) : "r"(so), "r"(j0));
                asm volatile("ld.shared::cluster.b64 %0, [%1];"
                             : "=l"(v) : "r"(ra) : "memory");
                *(ull*)(sHB + j0 * 256 + poff * 2) = v;
                asm("mapa.shared::cluster.u32 %0, %1, %2;"
                    : "=r"(ra) : "r"(so), "r"(j1));
                asm volatile("ld.shared::cluster.b64 %0, [%1];"
                             : "=l"(v) : "r"(ra) : "memory");
                *(ull*)(sHB + j1 * 256 + poff * 2) = v;
            }
            __syncthreads();  // sHB = h_{t+1} complete
        } // t

        // ---- final y from h_T (both layers) ----
        if (wid == 15) {
            float s0 = 0.f, s1 = 0.f, s2 = 0.f, s3 = 0.f;
#pragma unroll
            for (int i = 0; i < 8; i++) {
                int kk = lane + i * 32;
                float hv = sHB[kk * 8 + r];
                float4 fw = *(const float4*)&sFW[kk * 4];
                s0 += hv * fw.x; s1 += hv * fw.y;
                s2 += hv * fw.z; s3 += hv * fw.w;
            }
#pragma unroll
            for (int m = 16; m >= 1; m >>= 1) {
                s0 += __shfl_xor_sync(0xffffffffu, s0, m);
                s1 += __shfl_xor_sync(0xffffffffu, s1, m);
                s2 += __shfl_xor_sync(0xffffffffu, s2, m);
                s3 += __shfl_xor_sync(0xffffffffu, s3, m);
            }
            if (lane == 0) {
                s0 += sFB[0]; s1 += sFB[1]; s2 += sFB[2]; s3 += sFB[3];
                float nn = s0 * s0 + s1 * s1 + s2 * s2 + s3 * s3;
                float iv = 1.0f / fmaxf(sqrtf(nn), 1e-12f);
                if (l == 0) {
                    ((float4*)g_y1)[(cid * 8 + r) * TT + (TT - 1)] =
                        make_float4(s0 * iv, s1 * iv, s2 * iv, s3 * iv);
                } else {
                    ((float4*)out)[cid * 8 + r] =
                        make_float4(s0 * iv, s1 * iv, s2 * iv, s3 * iv);
                }
            }
        }
    } // l

    cluster_sync();   // no CTA exits while peers may still touch its SMEM
}

extern "C" void kernel_launch(void* const* d_in, const int* in_sizes, int n_in,
                              void* d_out, int out_size)
{
    (void)in_sizes; (void)n_in; (void)out_size;
    cudaFuncSetAttribute(qlstm_kernel,
                         cudaFuncAttributeMaxDynamicSharedMemorySize, SMEM_BYTES);
    qlstm_kernel<<<NCL * CLSZ, NTHR, SMEM_BYTES>>>(
        (const float*)d_in[0],
        (const float*)d_in[1], (const float*)d_in[2],
        (const float*)d_in[3], (const float*)d_in[4],
        (const float*)d_in[5],
        (const float*)d_in[6], (const float*)d_in[7],
        (const float*)d_in[8], (const float*)d_in[9],
        (const float*)d_in[10], (const float*)d_in[11],
        (float*)d_out);
}

// round 9
// speedup vs baseline: 1.9253x; 1.0009x over previous
#include <cuda_runtime.h>
#include <cstdint>

#define LL   2
#define TT   512
#define BB   128
#define HH   256
#define CLSZ 8
#define NCL  16
#define NTHR 512

// ---------------- smem layout (float indices) ----------------
#define OFF_U    0          // [128 col][260 pad h]         33280
#define OFF_HB   33280      // [256 h][8 b]                  2048
#define OFF_OUT  35328      // [2 parity][32 k][8 b]          512
#define OFF_PAR  35840      // [4 kq][8 b][128 col]          4096
#define OFF_WX   39936      // [128 col][4 f]                 512
#define OFF_WB   40448      // [128 col]                      128
#define OFF_FW   40576      // [256 k][4 f]                  1024
#define OFF_FB   41600      // [4]                              4
#define OFF_FLAG 41604      // [8] int step flags              8
#define SMEM_FLOATS 41612
#define SMEM_BYTES (SMEM_FLOATS * 4)

// layer-1 output scratch, TRANSPOSED: [B][T][4]
__device__ float g_y1[BB * TT * 4];

typedef unsigned long long ull;

__device__ __forceinline__ uint32_t smem_u32(const void* p) {
    uint32_t a;
    asm("{ .reg .u64 t; cvta.to.shared.u64 t, %1; cvt.u32.u64 %0, t; }"
        : "=r"(a) : "l"(p));
    return a;
}
__device__ __forceinline__ void cluster_sync() {
    asm volatile("barrier.cluster.arrive.aligned;" ::: "memory");
    asm volatile("barrier.cluster.wait.aligned;" ::: "memory");
}
__device__ __forceinline__ ull pack2(float a, float b) {
    ull r; asm("mov.b64 %0, {%1, %2};" : "=l"(r) : "f"(a), "f"(b)); return r;
}
__device__ __forceinline__ float2 unpack2(ull v) {
    float2 r; asm("mov.b64 {%0, %1}, %2;" : "=f"(r.x), "=f"(r.y) : "l"(v)); return r;
}
__device__ __forceinline__ ull ffma2(ull a, ull b, ull c) {
    ull d; asm("fma.rn.f32x2 %0, %1, %2, %3;" : "=l"(d) : "l"(a), "l"(b), "l"(c)); return d;
}
__device__ __forceinline__ float fsig(float x) {
    float e, r;
    asm("ex2.approx.f32 %0, %1;" : "=f"(e) : "f"(x * -1.4426950408889634f));
    asm("rcp.approx.f32 %0, %1;" : "=f"(r) : "f"(1.0f + e));
    return r;
}
__device__ __forceinline__ float ftanh(float x) {
    float e, r;
    asm("ex2.approx.f32 %0, %1;" : "=f"(e) : "f"(x * -2.8853900817779268f));
    asm("rcp.approx.f32 %0, %1;" : "=f"(r) : "f"(1.0f + e));
    return __fmaf_rn(2.0f, r, -1.0f);
}
// spin until local flag word >= target (peer writes via st.shared::cluster)
__device__ __forceinline__ void flag_spin(uint32_t fa, int target) {
    int v;
    do {
        asm volatile("ld.volatile.shared.b32 %0, [%1];" : "=r"(v) : "r"(fa));
    } while (v < target);
}

#define QNEG_MASK 0x284E

__global__ void __launch_bounds__(NTHR, 1) __cluster_dims__(CLSZ, 1, 1)
qlstm_kernel(const float* __restrict__ x,
             const float* __restrict__ Wxr, const float* __restrict__ Wxi,
             const float* __restrict__ Wxj, const float* __restrict__ Wxk,
             const float* __restrict__ Wxb,
             const float* __restrict__ Ur,  const float* __restrict__ Ui,
             const float* __restrict__ Uj,  const float* __restrict__ Uk,
             const float* __restrict__ fcw, const float* __restrict__ fcb,
             float* __restrict__ out)
{
    extern __shared__ float sm[];
    float* sU   = sm + OFF_U;
    float* sHB  = sm + OFF_HB;
    float* sOut = sm + OFF_OUT;
    float* sPar = sm + OFF_PAR;
    float* sWx  = sm + OFF_WX;
    float* sWb  = sm + OFF_WB;
    float* sFW  = sm + OFF_FW;
    float* sFB  = sm + OFF_FB;

    const int tid  = threadIdx.x;
    const int lane = tid & 31;
    const int wid  = tid >> 5;
    const int col  = tid & 127;        // GEMM column
    const int kq   = tid >> 7;         // split-K quarter
    const int r    = blockIdx.x & 7;
    const int cid  = blockIdx.x >> 3;
    const int k    = lane;             // activation k (tid<128)
    const int b0   = wid * 2;          // activation batch pair (warps 0..3)
    const int b1   = b0 + 1;
    const uint32_t sbase = smem_u32(sm);

    // pull-plan: thread handles (rank j0, off) and (rank j0+4, off)
    const int poff = tid & 127;        // b64 index within slice
    const int j0   = tid >> 7;         // 0..3
    const int j1   = j0 + 4;
    const uint32_t flag0 = sbase + (OFF_FLAG + j0) * 4;
    const uint32_t flag1 = sbase + (OFF_FLAG + j1) * 4;

    // ---- one-time init ----
    if (tid < 8) ((int*)(sm + OFF_FLAG))[tid] = 0;
    __syncthreads();
    cluster_sync();    // flags zeroed cluster-wide before any flag can arrive

    float2 creg;

    for (int l = 0; l < LL; l++) {
        __syncthreads();  // previous-phase readers done (incl. post-loop y-warp)

        // ---- gather U slice transposed+padded: sU[col*260 + h] ----
        for (int idx = tid; idx < 4 * 256 * 32; idx += NTHR) {
            int g   = idx >> 13;
            int rem = idx & 8191;
            int h   = rem >> 5;
            int kl  = rem & 31;
            int kg  = r * 32 + kl;
            int hb  = h >> 6, n = h & 63;
            int cb  = kg >> 6, m = kg & 63;
            int sel = hb ^ cb;
            float sgn = ((QNEG_MASK >> (cb * 4 + hb)) & 1) ? -1.0f : 1.0f;
            const float* cp = (sel == 0) ? Ur : (sel == 1) ? Ui : (sel == 2) ? Uj : Uk;
            sU[(g * 32 + kl) * 260 + h] =
                sgn * __ldg(&cp[((l * 4 + g) * 64 + n) * 64 + m]);
        }
        for (int idx = tid; idx < 512; idx += NTHR) {
            int g  = idx >> 7;
            int f  = (idx >> 5) & 3;
            int kl = idx & 31;
            int kg = r * 32 + kl;
            int cb = kg >> 6, m = kg & 63;
            int sel = f ^ cb;
            float sgn = ((QNEG_MASK >> (cb * 4 + f)) & 1) ? -1.0f : 1.0f;
            const float* cp = (sel == 0) ? Wxr : (sel == 1) ? Wxi : (sel == 2) ? Wxj : Wxk;
            sWx[(g * 32 + kl) * 4 + f] = sgn * __ldg(&cp[(l * 4 + g) * 64 + m]);
        }
        for (int idx = tid; idx < 128; idx += NTHR) {
            int g = idx >> 5, kl = idx & 31;
            sWb[idx] = Wxb[(l * 4 + g) * 256 + r * 32 + kl];
        }
        for (int idx = tid; idx < 1024; idx += NTHR)
            sFW[idx] = fcw[l * 1024 + idx];            // [256 k][4 f]
        if (tid < 4) sFB[tid] = fcb[l * 4 + tid];
        // zero h buffer (h_0 = 0); purely local — no cluster barrier needed
        for (int i = tid; i < 256 * 8; i += NTHR) sHB[i] = 0.0f;
        creg = make_float2(0.0f, 0.0f);
        __syncthreads();

        const float4* xp = (const float4*)((l == 0) ? x : g_y1);  // [B][T][4]

        for (int t = 0; t < TT; t++) {
            const float* hbc = sHB + kq * 512;         // kq*64 h × 8 b
            const float* up  = sU + col * 260 + kq * 64;

            // ---- y-warp: y_{t-1} = norm(fco(h_t)) (layer 0; overlaps GEMM) ----
            if (l == 0 && wid == 15 && t > 0) {
                float s0 = 0.f, s1 = 0.f, s2 = 0.f, s3 = 0.f;
#pragma unroll
                for (int i = 0; i < 8; i++) {
                    int kk = lane + i * 32;
                    float hv = sHB[kk * 8 + r];
                    float4 fw = *(const float4*)&sFW[kk * 4];
                    s0 += hv * fw.x; s1 += hv * fw.y;
                    s2 += hv * fw.z; s3 += hv * fw.w;
                }
#pragma unroll
                for (int m = 16; m >= 1; m >>= 1) {
                    s0 += __shfl_xor_sync(0xffffffffu, s0, m);
                    s1 += __shfl_xor_sync(0xffffffffu, s1, m);
                    s2 += __shfl_xor_sync(0xffffffffu, s2, m);
                    s3 += __shfl_xor_sync(0xffffffffu, s3, m);
                }
                if (lane == 0) {
                    s0 += sFB[0]; s1 += sFB[1]; s2 += sFB[2]; s3 += sFB[3];
                    float nn = s0 * s0 + s1 * s1 + s2 * s2 + s3 * s3;
                    float iv = 1.0f / fmaxf(sqrtf(nn), 1e-12f);
                    ((float4*)g_y1)[(cid * 8 + r) * TT + (t - 1)] =
                        make_float4(s0 * iv, s1 * iv, s2 * iv, s3 * iv);
                }
            }

            // ---- acc init: kq==0 adds bias + x_t @ Wx ----
            ull A0, A1, A2, A3;
            if (kq == 0) {
                float4 wxc = *(const float4*)&sWx[col * 4];
                float  wbc = sWb[col];
                float acc[8];
#pragma unroll
                for (int j = 0; j < 8; j++) {
                    float4 xv = __ldg(&xp[(cid * 8 + j) * TT + t]);
                    acc[j] = wbc + xv.x * wxc.x + xv.y * wxc.y
                                 + xv.z * wxc.z + xv.w * wxc.w;
                }
                A0 = pack2(acc[0], acc[1]); A1 = pack2(acc[2], acc[3]);
                A2 = pack2(acc[4], acc[5]); A3 = pack2(acc[6], acc[7]);
            } else {
                A0 = A1 = A2 = A3 = 0ull;
            }

            // ---- GEMM quarter: 64 h × 8 batches ----
#pragma unroll
            for (int hh = 0; hh < 64; hh += 4) {
                float4 u4 = *(const float4*)(up + hh);
                const float* hp = hbc + hh * 8;
                {
                    ull uu = pack2(u4.x, u4.x);
                    ulonglong2 a = *(const ulonglong2*)(hp);
                    ulonglong2 b = *(const ulonglong2*)(hp + 4);
                    A0 = ffma2(a.x, uu, A0); A1 = ffma2(a.y, uu, A1);
                    A2 = ffma2(b.x, uu, A2); A3 = ffma2(b.y, uu, A3);
                }
                {
                    ull uu = pack2(u4.y, u4.y);
                    ulonglong2 a = *(const ulonglong2*)(hp + 8);
                    ulonglong2 b = *(const ulonglong2*)(hp + 12);
                    A0 = ffma2(a.x, uu, A0); A1 = ffma2(a.y, uu, A1);
                    A2 = ffma2(b.x, uu, A2); A3 = ffma2(b.y, uu, A3);
                }
                {
                    ull uu = pack2(u4.z, u4.z);
                    ulonglong2 a = *(const ulonglong2*)(hp + 16);
                    ulonglong2 b = *(const ulonglong2*)(hp + 20);
                    A0 = ffma2(a.x, uu, A0); A1 = ffma2(a.y, uu, A1);
                    A2 = ffma2(b.x, uu, A2); A3 = ffma2(b.y, uu, A3);
                }
                {
                    ull uu = pack2(u4.w, u4.w);
                    ulonglong2 a = *(const ulonglong2*)(hp + 24);
                    ulonglong2 b = *(const ulonglong2*)(hp + 28);
                    A0 = ffma2(a.x, uu, A0); A1 = ffma2(a.y, uu, A1);
                    A2 = ffma2(b.x, uu, A2); A3 = ffma2(b.y, uu, A3);
                }
            }

            // ---- write partials: sPar[kq][b][col] ----
            {
                float* pp = sPar + kq * 1024 + col;
                float2 v;
                v = unpack2(A0); pp[0 * 128] = v.x; pp[1 * 128] = v.y;
                v = unpack2(A1); pp[2 * 128] = v.x; pp[3 * 128] = v.y;
                v = unpack2(A2); pp[4 * 128] = v.x; pp[5 * 128] = v.y;
                v = unpack2(A3); pp[6 * 128] = v.x; pp[7 * 128] = v.y;
            }
            __syncthreads();

            // ---- combine + activations + LOCAL h store (tid<128) ----
            if (tid < 128) {
                float hn0, hn1;
#pragma unroll
                for (int bi = 0; bi < 2; bi++) {
                    const int b = bi ? b1 : b0;
                    const float* pb = sPar + b * 128 + k;
                    float pf = 0.f, pi = 0.f, po = 0.f, pc = 0.f;
#pragma unroll
                    for (int q = 0; q < 4; q++) {
                        const float* pq = pb + q * 1024;
                        pf += pq[0];
                        pi += pq[32];
                        po += pq[64];
                        pc += pq[96];
                    }
                    float ft = fsig(pf);
                    float it = fsig(pi);
                    float ot = fsig(po);
                    float ct = ftanh(pc);
                    float cold = bi ? creg.y : creg.x;
                    float c  = it * ct + ft * cold;
                    if (bi) creg.y = c; else creg.x = c;
                    float hn = ot * ftanh(c);
                    if (bi) hn1 = hn; else hn0 = hn;
                }
                *(ull*)(sOut + (t & 1) * 256 + k * 8 + b0) = pack2(hn0, hn1);
            }

            __syncthreads();   // drains sOut STS to SMEM (HW-native on BAR)

            // ---- publish: push step flag to all 8 ranks (monotonic, no ABA) ----
            const int gs = l * TT + t + 1;
            if (tid == 0) {
                uint32_t fa = sbase + (OFF_FLAG + r) * 4;
#pragma unroll
                for (int j = 0; j < CLSZ; j++) {
                    uint32_t ra;
                    asm("mapa.shared::cluster.u32 %0, %1, %2;"
                        : "=r"(ra) : "r"(fa), "r"(j));
                    asm volatile("st.shared::cluster.b32 [%0], %1;"
                                 :: "r"(ra), "r"(gs) : "memory");
                }
            }

            // ---- spin on the 2 source ranks this thread pulls from ----
            flag_spin(flag0, gs);
            flag_spin(flag1, gs);

            // ---- pull both slices into local sHB ----
            {
                const uint32_t so = sbase + (OFF_OUT + (t & 1) * 256) * 4 + poff * 8;
                uint32_t ra; ull v;
                asm("mapa.shared::cluster.u32 %0, %1, %2;"
                    : "=r"(ra) : "r"(so), "r"(j0));
                asm volatile("ld.shared::cluster.b64 %0, [%1];"
                             : "=l"(v) : "r"(ra) : "memory");
                *(ull*)(sHB + j0 * 256 + poff * 2) = v;
                asm("mapa.shared::cluster.u32 %0, %1, %2;"
                    : "=r"(ra) : "r"(so), "r"(j1));
                asm volatile("ld.shared::cluster.b64 %0, [%1];"
                             : "=l"(v) : "r"(ra) : "memory");
                *(ull*)(sHB + j1 * 256 + poff * 2) = v;
            }
            __syncthreads();  // sHB = h_{t+1} complete
        } // t

        // ---- final y from h_T (both layers) ----
        if (wid == 15) {
            float s0 = 0.f, s1 = 0.f, s2 = 0.f, s3 = 0.f;
#pragma unroll
            for (int i = 0; i < 8; i++) {
                int kk = lane + i * 32;
                float hv = sHB[kk * 8 + r];
                float4 fw = *(const float4*)&sFW[kk * 4];
                s0 += hv * fw.x; s1 += hv * fw.y;
                s2 += hv * fw.z; s3 += hv * fw.w;
            }
#pragma unroll
            for (int m = 16; m >= 1; m >>= 1) {
                s0 += __shfl_xor_sync(0xffffffffu, s0, m);
                s1 += __shfl_xor_sync(0xffffffffu, s1, m);
                s2 += __shfl_xor_sync(0xffffffffu, s2, m);
                s3 += __shfl_xor_sync(0xffffffffu, s3, m);
            }
            if (lane == 0) {
                s0 += sFB[0]; s1 += sFB[1]; s2 += sFB[2]; s3 += sFB[3];
                float nn = s0 * s0 + s1 * s1 + s2 * s2 + s3 * s3;
                float iv = 1.0f / fmaxf(sqrtf(nn), 1e-12f);
                if (l == 0) {
                    ((float4*)g_y1)[(cid * 8 + r) * TT + (TT - 1)] =
                        make_float4(s0 * iv, s1 * iv, s2 * iv, s3 * iv);
                } else {
                    ((float4*)out)[cid * 8 + r] =
                        make_float4(s0 * iv, s1 * iv, s2 * iv, s3 * iv);
                }
            }
        }
    } // l

    cluster_sync();   // no CTA exits while peers may still touch its SMEM
}

extern "C" void kernel_launch(void* const* d_in, const int* in_sizes, int n_in,
                              void* d_out, int out_size)
{
    (void)in_sizes; (void)n_in; (void)out_size;
    cudaFuncSetAttribute(qlstm_kernel,
                         cudaFuncAttributeMaxDynamicSharedMemorySize, SMEM_BYTES);
    qlstm_kernel<<<NCL * CLSZ, NTHR, SMEM_BYTES>>>(
        (const float*)d_in[0],
        (const float*)d_in[1], (const float*)d_in[2],
        (const float*)d_in[3], (const float*)d_in[4],
        (const float*)d_in[5],
        (const float*)d_in[6], (const float*)d_in[7],
        (const float*)d_in[8], (const float*)d_in[9],
        (const float*)d_in[10], (const float*)d_in[11],
        (float*)d_out);
}